// round 1
// baseline (speedup 1.0000x reference)
#include <cuda_runtime.h>
#include <math.h>

// ---------------------------------------------------------------------------
// Problem shapes (fixed)
//   x: (16, 512, 32, 32)  -> (B=16, C=512, N=1024)
//   GROUPS=32, HEADS=4, HD=128
// ---------------------------------------------------------------------------
#define B_   16
#define C_   512
#define N_   1024
#define HEADS 4
#define HD   128
#define GROUPS 32
#define GSIZE (C_ / GROUPS)          // 16 channels per group
#define QKV_C (3 * C_)               // 1536

// Scratch (device globals — allocation-free per harness rules)
__device__ float g_y  [(size_t)B_ * C_ * N_];        // groupnorm output (32 MB)
__device__ float g_qkv[(size_t)B_ * QKV_C * N_];     // qkv (100 MB)
__device__ float g_s  [(size_t)B_ * HEADS * N_ * N_];// scores (256 MB)
__device__ float g_o  [(size_t)B_ * C_ * N_];        // attn output (32 MB)

// ---------------------------------------------------------------------------
// GroupNorm: one block per (b, group). Group data is 16*1024 = 16384
// contiguous floats.
// ---------------------------------------------------------------------------
__global__ void groupnorm_kernel(const float* __restrict__ x,
                                 const float* __restrict__ w,
                                 const float* __restrict__ bias,
                                 float* __restrict__ y)
{
    const int blk = blockIdx.x;              // b*GROUPS + g
    const int g   = blk % GROUPS;
    const long base = (long)blk * (GSIZE * N_);
    const float* xp = x + base;
    float* yp = y + base;

    const int tid = threadIdx.x;             // 256 threads
    float s = 0.f, s2 = 0.f;
    #pragma unroll 8
    for (int i = tid; i < GSIZE * N_; i += 256) {
        float v = xp[i];
        s += v; s2 += v * v;
    }
    // reduce
    __shared__ float rs[32], rs2[32];
    for (int off = 16; off > 0; off >>= 1) {
        s  += __shfl_down_sync(0xffffffffu, s,  off);
        s2 += __shfl_down_sync(0xffffffffu, s2, off);
    }
    if ((tid & 31) == 0) { rs[tid >> 5] = s; rs2[tid >> 5] = s2; }
    __syncthreads();
    if (tid < 32) {
        s  = (tid < 8) ? rs[tid]  : 0.f;
        s2 = (tid < 8) ? rs2[tid] : 0.f;
        for (int off = 4; off > 0; off >>= 1) {
            s  += __shfl_down_sync(0xffffffffu, s,  off);
            s2 += __shfl_down_sync(0xffffffffu, s2, off);
        }
        if (tid == 0) { rs[0] = s; rs2[0] = s2; }
    }
    __syncthreads();
    const float inv_n = 1.0f / (GSIZE * N_);
    const float mean  = rs[0] * inv_n;
    const float var   = rs2[0] * inv_n - mean * mean;
    const float rstd  = rsqrtf(var + 1e-5f);

    const int c0 = g * GSIZE;
    #pragma unroll 4
    for (int i = tid; i < GSIZE * N_; i += 256) {
        int ch = c0 + (i >> 10);             // i / 1024
        yp[i] = (xp[i] - mean) * rstd * w[ch] + bias[ch];
    }
}

// ---------------------------------------------------------------------------
// Generic batched tiled fp32 GEMM:
//   C[z] = alpha * op(A[z]) @ op(B[z]) (+ bias[m]) (+ R[z][m,n])
// Batch offset: z -> (z/inner)*s?o + (z%inner)*s?i  (handles (b,h) batching)
// BM=BN=64, BK=16, 256 threads, 4x4 micro-tile per thread.
// EPI: 0 = none, 1 = +bias[m], 2 = +bias[m] + residual
// ---------------------------------------------------------------------------
#define BM 64
#define BN 64
#define BK 16
#define TM 4
#define TN 4

template<bool TA, bool TB, int EPI>
__global__ void gemm_kernel(const float* __restrict__ A,
                            const float* __restrict__ B,
                            float* __restrict__ C,
                            int M, int N, int K,
                            int lda, int ldb, int ldc,
                            int inner,
                            long sAo, long sAi, long sBo, long sBi,
                            long sCo, long sCi,
                            float alpha,
                            const float* __restrict__ bias,
                            const float* __restrict__ R,
                            long sRo, long sRi)
{
    const int z  = blockIdx.z;
    const int zo = z / inner, zi = z % inner;
    A += zo * sAo + zi * sAi;
    B += zo * sBo + zi * sBi;
    C += zo * sCo + zi * sCi;
    if (EPI == 2) R += zo * sRo + zi * sRi;

    __shared__ float As[BK][BM];
    __shared__ float Bs[BK][BN];

    const int tid = threadIdx.x;             // 256
    const int tx = tid & 15;                 // 0..15 (n)
    const int ty = tid >> 4;                 // 0..15 (m)
    const int m0 = blockIdx.y * BM;
    const int n0 = blockIdx.x * BN;

    float acc[TM][TN];
    #pragma unroll
    for (int i = 0; i < TM; i++)
        #pragma unroll
        for (int j = 0; j < TN; j++) acc[i][j] = 0.f;

    for (int k0 = 0; k0 < K; k0 += BK) {
        // --- load A tile (coalesced for both layouts) ---
        #pragma unroll
        for (int it = 0; it < (BM * BK) / 256; it++) {
            int idx = tid + it * 256;
            int m, k;
            if (TA) { m = idx % BM; k = idx / BM; }   // A[k*lda+m]: m fastest
            else    { k = idx % BK; m = idx / BK; }   // A[m*lda+k]: k fastest
            int gm = m0 + m, gk = k0 + k;
            float v = 0.f;
            if (gm < M && gk < K)
                v = TA ? A[(long)gk * lda + gm] : A[(long)gm * lda + gk];
            As[k][m] = v;
        }
        // --- load B tile ---
        #pragma unroll
        for (int it = 0; it < (BK * BN) / 256; it++) {
            int idx = tid + it * 256;
            int k, n;
            if (TB) { k = idx % BK; n = idx / BK; }   // B[n*ldb+k]: k fastest
            else    { n = idx % BN; k = idx / BN; }   // B[k*ldb+n]: n fastest
            int gk = k0 + k, gn = n0 + n;
            float v = 0.f;
            if (gk < K && gn < N)
                v = TB ? B[(long)gn * ldb + gk] : B[(long)gk * ldb + gn];
            Bs[k][n] = v;
        }
        __syncthreads();

        #pragma unroll
        for (int k = 0; k < BK; k++) {
            float ra[TM], rb[TN];
            #pragma unroll
            for (int i = 0; i < TM; i++) ra[i] = As[k][ty * TM + i];
            #pragma unroll
            for (int j = 0; j < TN; j++) rb[j] = Bs[k][tx * TN + j];
            #pragma unroll
            for (int i = 0; i < TM; i++)
                #pragma unroll
                for (int j = 0; j < TN; j++)
                    acc[i][j] += ra[i] * rb[j];
        }
        __syncthreads();
    }

    // --- epilogue ---
    #pragma unroll
    for (int i = 0; i < TM; i++) {
        int gm = m0 + ty * TM + i;
        if (gm >= M) continue;
        float bv = (EPI >= 1) ? bias[gm] : 0.f;
        #pragma unroll
        for (int j = 0; j < TN; j++) {
            int gn = n0 + tx * TN + j;
            if (gn >= N) continue;
            float v = acc[i][j] * alpha + bv;
            if (EPI == 2) v += R[(long)gm * ldc + gn];
            C[(long)gm * ldc + gn] = v;
        }
    }
}

// ---------------------------------------------------------------------------
// Row softmax over N_=1024 elements. One block (256 thr) per row.
// ---------------------------------------------------------------------------
__global__ void softmax_kernel(float* __restrict__ S)
{
    float* p = S + (size_t)blockIdx.x * N_;
    const int tid = threadIdx.x;

    float v[4];
    float mx = -3.4e38f;
    #pragma unroll
    for (int i = 0; i < 4; i++) { v[i] = p[tid + i * 256]; mx = fmaxf(mx, v[i]); }

    __shared__ float red[32];
    for (int off = 16; off > 0; off >>= 1)
        mx = fmaxf(mx, __shfl_xor_sync(0xffffffffu, mx, off));
    if ((tid & 31) == 0) red[tid >> 5] = mx;
    __syncthreads();
    if (tid < 32) {
        float m = (tid < 8) ? red[tid] : -3.4e38f;
        for (int off = 4; off > 0; off >>= 1)
            m = fmaxf(m, __shfl_xor_sync(0xffffffffu, m, off));
        if (tid == 0) red[0] = m;
    }
    __syncthreads();
    mx = red[0];

    float s = 0.f;
    #pragma unroll
    for (int i = 0; i < 4; i++) { v[i] = expf(v[i] - mx); s += v[i]; }
    for (int off = 16; off > 0; off >>= 1)
        s += __shfl_xor_sync(0xffffffffu, s, off);
    __shared__ float red2[32];
    if ((tid & 31) == 0) red2[tid >> 5] = s;
    __syncthreads();
    if (tid < 32) {
        float t = (tid < 8) ? red2[tid] : 0.f;
        for (int off = 4; off > 0; off >>= 1)
            t += __shfl_xor_sync(0xffffffffu, t, off);
        if (tid == 0) red2[0] = t;
    }
    __syncthreads();
    const float inv = 1.0f / red2[0];
    #pragma unroll
    for (int i = 0; i < 4; i++) p[tid + i * 256] = v[i] * inv;
}

// ---------------------------------------------------------------------------
// Launch
// ---------------------------------------------------------------------------
extern "C" void kernel_launch(void* const* d_in, const int* in_sizes, int n_in,
                              void* d_out, int out_size)
{
    const float* x      = (const float*)d_in[0];
    const float* norm_w = (const float*)d_in[1];
    const float* norm_b = (const float*)d_in[2];
    const float* qkv_w  = (const float*)d_in[3];
    const float* qkv_b  = (const float*)d_in[4];
    const float* proj_w = (const float*)d_in[5];
    const float* proj_b = (const float*)d_in[6];
    float* out          = (float*)d_out;

    float *y, *qkv, *s, *o;
    cudaGetSymbolAddress((void**)&y,   g_y);
    cudaGetSymbolAddress((void**)&qkv, g_qkv);
    cudaGetSymbolAddress((void**)&s,   g_s);
    cudaGetSymbolAddress((void**)&o,   g_o);

    // 1) GroupNorm -> y (B, C, N)
    groupnorm_kernel<<<B_ * GROUPS, 256>>>(x, norm_w, norm_b, y);

    // 2) QKV GEMM: qkv[b](1536,1024) = qkv_w(1536,512) @ y[b](512,1024) + qkv_b
    {
        dim3 grid(N_ / BN, QKV_C / BM, B_);
        gemm_kernel<false, false, 1><<<grid, 256>>>(
            qkv_w, y, qkv,
            QKV_C, N_, C_, C_, N_, N_,
            /*inner*/1, /*sAo*/0, 0, /*sBo*/(long)C_ * N_, 0,
            /*sCo*/(long)QKV_C * N_, 0,
            1.0f, qkv_b, nullptr, 0, 0);
    }

    // 3) Scores: S[b,h](1024,1024) = Q^T @ K * scale
    //    Q at qkv + b*1536*1024 + h*128*1024 ; K at +512*1024 ; V at +1024*1024
    const float scale = 0.08838834764831845f;   // 128^-0.5
    {
        dim3 grid(N_ / BN, N_ / BM, B_ * HEADS);
        gemm_kernel<true, false, 0><<<grid, 256>>>(
            qkv /*Q*/, qkv + (long)C_ * N_ /*K*/, s,
            N_, N_, HD, N_, N_, N_,
            /*inner*/HEADS,
            /*sAo*/(long)QKV_C * N_, /*sAi*/(long)HD * N_,
            /*sBo*/(long)QKV_C * N_, /*sBi*/(long)HD * N_,
            /*sCo*/(long)HEADS * N_ * N_, /*sCi*/(long)N_ * N_,
            scale, nullptr, nullptr, 0, 0);
    }

    // 4) Softmax over key dim (rows of S)
    softmax_kernel<<<B_ * HEADS * N_, 256>>>(s);

    // 5) O[b,h](128,1024) = V(128,1024) @ S^T(1024,1024)
    {
        dim3 grid(N_ / BN, HD / BM, B_ * HEADS);
        gemm_kernel<false, true, 0><<<grid, 256>>>(
            qkv + 2L * C_ * N_ /*V*/, s, o,
            HD, N_, N_, N_, N_, N_,
            /*inner*/HEADS,
            /*sAo*/(long)QKV_C * N_, /*sAi*/(long)HD * N_,
            /*sBo*/(long)HEADS * N_ * N_, /*sBi*/(long)N_ * N_,
            /*sCo*/(long)C_ * N_, /*sCi*/(long)HD * N_,
            1.0f, nullptr, nullptr, 0, 0);
    }

    // 6) out[b](512,1024) = proj_w(512,512) @ o[b](512,1024) + proj_b + x[b]
    {
        dim3 grid(N_ / BN, C_ / BM, B_);
        gemm_kernel<false, false, 2><<<grid, 256>>>(
            proj_w, o, out,
            C_, N_, C_, C_, N_, N_,
            /*inner*/1, 0, 0, /*sBo*/(long)C_ * N_, 0,
            /*sCo*/(long)C_ * N_, 0,
            1.0f, proj_b, x, /*sRo*/(long)C_ * N_, 0);
    }
}

// round 2
// speedup vs baseline: 2.1534x; 2.1534x over previous
#include <cuda_runtime.h>
#include <mma.h>
#include <math.h>
#include <type_traits>

using namespace nvcuda;

// ---------------------------------------------------------------------------
// Shapes (fixed): x (16, 512, 32, 32) -> B=16, C=512, N=1024; heads=4, hd=128
// ---------------------------------------------------------------------------
#define B_   16
#define C_   512
#define N_   1024
#define HEADS 4
#define HD   128
#define GROUPS 32
#define GSIZE (C_ / GROUPS)
#define QKV_C (3 * C_)

// Scratch (device globals — allocation-free per harness rules)
__device__ float g_y  [(size_t)B_ * C_ * N_];
__device__ float g_qkv[(size_t)B_ * QKV_C * N_];
__device__ float g_s  [(size_t)B_ * HEADS * N_ * N_];
__device__ float g_o  [(size_t)B_ * C_ * N_];

// ---------------------------------------------------------------------------
// GroupNorm
// ---------------------------------------------------------------------------
__global__ void groupnorm_kernel(const float* __restrict__ x,
                                 const float* __restrict__ w,
                                 const float* __restrict__ bias,
                                 float* __restrict__ y)
{
    const int blk = blockIdx.x;
    const int g   = blk % GROUPS;
    const long base = (long)blk * (GSIZE * N_);
    const float* xp = x + base;
    float* yp = y + base;

    const int tid = threadIdx.x;
    float s = 0.f, s2 = 0.f;
    #pragma unroll 8
    for (int i = tid; i < GSIZE * N_; i += 256) {
        float v = xp[i];
        s += v; s2 += v * v;
    }
    __shared__ float rs[32], rs2[32];
    for (int off = 16; off > 0; off >>= 1) {
        s  += __shfl_down_sync(0xffffffffu, s,  off);
        s2 += __shfl_down_sync(0xffffffffu, s2, off);
    }
    if ((tid & 31) == 0) { rs[tid >> 5] = s; rs2[tid >> 5] = s2; }
    __syncthreads();
    if (tid < 32) {
        s  = (tid < 8) ? rs[tid]  : 0.f;
        s2 = (tid < 8) ? rs2[tid] : 0.f;
        for (int off = 4; off > 0; off >>= 1) {
            s  += __shfl_down_sync(0xffffffffu, s,  off);
            s2 += __shfl_down_sync(0xffffffffu, s2, off);
        }
        if (tid == 0) { rs[0] = s; rs2[0] = s2; }
    }
    __syncthreads();
    const float inv_n = 1.0f / (GSIZE * N_);
    const float mean  = rs[0] * inv_n;
    const float var   = rs2[0] * inv_n - mean * mean;
    const float rstd  = rsqrtf(var + 1e-5f);

    const int c0 = g * GSIZE;
    #pragma unroll 4
    for (int i = tid; i < GSIZE * N_; i += 256) {
        int ch = c0 + (i >> 10);
        yp[i] = (xp[i] - mean) * rstd * w[ch] + bias[ch];
    }
}

// ---------------------------------------------------------------------------
// Tile copy GMEM -> SMEM, float4-vectorized, optional tf32 rounding.
// ---------------------------------------------------------------------------
template<int ROWS, int COLS, bool CVT>
__device__ __forceinline__ void tile_copy(float* dst, int sld,
                                          const float* src, long gld, int tid)
{
    constexpr int CV = COLS / 4;
    constexpr int NV = ROWS * CV;
    #pragma unroll
    for (int i = tid; i < NV; i += 256) {
        int r = i / CV, c = i % CV;
        float4 v = *reinterpret_cast<const float4*>(src + (long)r * gld + c * 4);
        if (CVT) {
            v.x = wmma::__float_to_tf32(v.x);
            v.y = wmma::__float_to_tf32(v.y);
            v.z = wmma::__float_to_tf32(v.z);
            v.w = wmma::__float_to_tf32(v.w);
        }
        *reinterpret_cast<float4*>(dst + r * sld + c * 4) = v;
    }
}

// ---------------------------------------------------------------------------
// TF32 wmma GEMM:  C[z] = alpha * op(A[z]) @ op(B[z]) (+ bias[m]) (+ R[z])
// A_COL: A stored so element(m,k) is at A[k*lda + m] (col-major view)
// B_COL: element(k,n) at B[n*ldb + k]
// BM=128, BK=32, BN template (128 for EPI=0, 64 for staged epilogues).
// 8 warps (4 m x 2 n); warp tile 32 x (BN/2).
// ---------------------------------------------------------------------------
template<bool A_COL, bool B_COL, int EPI, int BN>
__global__ void __launch_bounds__(256)
wgemm(const float* __restrict__ A, const float* __restrict__ B,
      float* __restrict__ C, int K, long lda, long ldb, long ldc,
      int inner,
      long sAo, long sAi, long sBo, long sBi, long sCo, long sCi,
      float alpha, const float* __restrict__ bias,
      const float* __restrict__ R, long sRo)
{
    constexpr int BM = 128, BK = 32, PAD = 4;
    constexpr int ldA = A_COL ? (BM + PAD) : (BK + PAD);
    constexpr int ldB = B_COL ? (BK + PAD) : (BN + PAD);
    constexpr int AsE = A_COL ? BK * (BM + PAD) : BM * (BK + PAD);
    constexpr int BsE = B_COL ? BN * (BK + PAD) : BK * (BN + PAD);
    constexpr int StE = (EPI > 0) ? BM * (BN + PAD) : 1;
    constexpr int SmE = (AsE + BsE > StE) ? (AsE + BsE) : StE;
    constexpr int NT  = BN / 32;          // n-frags per warp
    __shared__ float sm[SmE];
    float* As = sm;
    float* Bs = sm + AsE;

    const int z  = blockIdx.z;
    const int zo = z / inner, zi = z % inner;
    A += zo * sAo + zi * sAi;
    B += zo * sBo + zi * sBi;
    C += zo * sCo + zi * sCi;
    if (EPI == 2) R += zo * sRo;

    const int tid = threadIdx.x;
    const int w   = tid >> 5;
    const int wm  = w >> 1;               // 0..3
    const int wn  = w & 1;                // 0..1
    const int m0  = blockIdx.y * BM;
    const int n0  = blockIdx.x * BN;

    using AL = typename std::conditional<A_COL, wmma::col_major, wmma::row_major>::type;
    using BL = typename std::conditional<B_COL, wmma::col_major, wmma::row_major>::type;

    wmma::fragment<wmma::accumulator, 16, 16, 8, float> acc[2][NT];
    #pragma unroll
    for (int i = 0; i < 2; i++)
        #pragma unroll
        for (int j = 0; j < NT; j++) wmma::fill_fragment(acc[i][j], 0.0f);

    for (int k0 = 0; k0 < K; k0 += BK) {
        if (A_COL) tile_copy<BK, BM, true>(As, ldA, A + (long)k0 * lda + m0, lda, tid);
        else       tile_copy<BM, BK, true>(As, ldA, A + (long)m0 * lda + k0, lda, tid);
        if (B_COL) tile_copy<BN, BK, true>(Bs, ldB, B + (long)n0 * ldb + k0, ldb, tid);
        else       tile_copy<BK, BN, true>(Bs, ldB, B + (long)k0 * ldb + n0, ldb, tid);
        __syncthreads();

        #pragma unroll
        for (int kk = 0; kk < BK; kk += 8) {
            wmma::fragment<wmma::matrix_a, 16, 16, 8, wmma::precision::tf32, AL> af[2];
            wmma::fragment<wmma::matrix_b, 16, 16, 8, wmma::precision::tf32, BL> bf[NT];
            #pragma unroll
            for (int i = 0; i < 2; i++) {
                const float* p = A_COL ? (As + kk * ldA + (wm * 32 + i * 16))
                                       : (As + (wm * 32 + i * 16) * ldA + kk);
                wmma::load_matrix_sync(af[i], p, ldA);
            }
            #pragma unroll
            for (int j = 0; j < NT; j++) {
                int n = wn * (BN / 2) + j * 16;
                const float* p = B_COL ? (Bs + n * ldB + kk)
                                       : (Bs + kk * ldB + n);
                wmma::load_matrix_sync(bf[j], p, ldB);
            }
            #pragma unroll
            for (int i = 0; i < 2; i++)
                #pragma unroll
                for (int j = 0; j < NT; j++)
                    wmma::mma_sync(acc[i][j], af[i], bf[j], acc[i][j]);
        }
        __syncthreads();
    }

    // alpha scale
    #pragma unroll
    for (int i = 0; i < 2; i++)
        #pragma unroll
        for (int j = 0; j < NT; j++)
            #pragma unroll
            for (int t = 0; t < acc[i][j].num_elements; t++)
                acc[i][j].x[t] *= alpha;

    if (EPI == 0) {
        #pragma unroll
        for (int i = 0; i < 2; i++)
            #pragma unroll
            for (int j = 0; j < NT; j++) {
                int gm = m0 + wm * 32 + i * 16;
                int gn = n0 + wn * (BN / 2) + j * 16;
                wmma::store_matrix_sync(C + (long)gm * ldc + gn, acc[i][j],
                                        (unsigned)ldc, wmma::mem_row_major);
            }
    } else {
        float* St = sm;                     // reuse load smem (post-sync)
        constexpr int ldS = BN + PAD;
        #pragma unroll
        for (int i = 0; i < 2; i++)
            #pragma unroll
            for (int j = 0; j < NT; j++)
                wmma::store_matrix_sync(St + (wm * 32 + i * 16) * ldS
                                           + wn * (BN / 2) + j * 16,
                                        acc[i][j], ldS, wmma::mem_row_major);
        __syncthreads();
        constexpr int CV = BN / 4;
        #pragma unroll
        for (int i = tid; i < BM * CV; i += 256) {
            int r = i / CV, c = i % CV;
            int gm = m0 + r, gn = n0 + c * 4;
            float4 v = *reinterpret_cast<const float4*>(St + r * ldS + c * 4);
            float bv = bias[gm];
            v.x += bv; v.y += bv; v.z += bv; v.w += bv;
            if (EPI == 2) {
                float4 rv = *reinterpret_cast<const float4*>(R + (long)gm * ldc + gn);
                v.x += rv.x; v.y += rv.y; v.z += rv.z; v.w += rv.w;
            }
            *reinterpret_cast<float4*>(C + (long)gm * ldc + gn) = v;
        }
    }
}

// ---------------------------------------------------------------------------
// Row softmax over 1024 elements. One block (256 thr) per row.
// ---------------------------------------------------------------------------
__global__ void softmax_kernel(float* __restrict__ S)
{
    float* p = S + (size_t)blockIdx.x * N_;
    const int tid = threadIdx.x;

    float v[4];
    float mx = -3.4e38f;
    #pragma unroll
    for (int i = 0; i < 4; i++) { v[i] = p[tid + i * 256]; mx = fmaxf(mx, v[i]); }

    __shared__ float red[32];
    for (int off = 16; off > 0; off >>= 1)
        mx = fmaxf(mx, __shfl_xor_sync(0xffffffffu, mx, off));
    if ((tid & 31) == 0) red[tid >> 5] = mx;
    __syncthreads();
    if (tid < 32) {
        float m = (tid < 8) ? red[tid] : -3.4e38f;
        for (int off = 4; off > 0; off >>= 1)
            m = fmaxf(m, __shfl_xor_sync(0xffffffffu, m, off));
        if (tid == 0) red[0] = m;
    }
    __syncthreads();
    mx = red[0];

    float s = 0.f;
    #pragma unroll
    for (int i = 0; i < 4; i++) { v[i] = expf(v[i] - mx); s += v[i]; }
    for (int off = 16; off > 0; off >>= 1)
        s += __shfl_xor_sync(0xffffffffu, s, off);
    __shared__ float red2[32];
    if ((tid & 31) == 0) red2[tid >> 5] = s;
    __syncthreads();
    if (tid < 32) {
        float t = (tid < 8) ? red2[tid] : 0.f;
        for (int off = 4; off > 0; off >>= 1)
            t += __shfl_xor_sync(0xffffffffu, t, off);
        if (tid == 0) red2[0] = t;
    }
    __syncthreads();
    const float inv = 1.0f / red2[0];
    #pragma unroll
    for (int i = 0; i < 4; i++) p[tid + i * 256] = v[i] * inv;
}

// ---------------------------------------------------------------------------
// Launch
// ---------------------------------------------------------------------------
extern "C" void kernel_launch(void* const* d_in, const int* in_sizes, int n_in,
                              void* d_out, int out_size)
{
    const float* x      = (const float*)d_in[0];
    const float* norm_w = (const float*)d_in[1];
    const float* norm_b = (const float*)d_in[2];
    const float* qkv_w  = (const float*)d_in[3];
    const float* qkv_b  = (const float*)d_in[4];
    const float* proj_w = (const float*)d_in[5];
    const float* proj_b = (const float*)d_in[6];
    float* out          = (float*)d_out;

    float *y, *qkv, *s, *o;
    cudaGetSymbolAddress((void**)&y,   g_y);
    cudaGetSymbolAddress((void**)&qkv, g_qkv);
    cudaGetSymbolAddress((void**)&s,   g_s);
    cudaGetSymbolAddress((void**)&o,   g_o);

    // 1) GroupNorm
    groupnorm_kernel<<<B_ * GROUPS, 256>>>(x, norm_w, norm_b, y);

    // 2) QKV: qkv[b](1536,1024) = qkv_w(1536,512) @ y[b] + qkv_b
    {
        dim3 grid(N_ / 64, QKV_C / 128, B_);
        wgemm<false, false, 1, 64><<<grid, 256>>>(
            qkv_w, y, qkv, C_, C_, N_, N_,
            1, 0, 0, (long)C_ * N_, 0, (long)QKV_C * N_, 0,
            1.0f, qkv_b, nullptr, 0);
    }

    // 3) S[b,h](1024,1024) = Q^T @ K * scale  (A col-major view of Q)
    const float scale = 0.08838834764831845f;
    {
        dim3 grid(N_ / 128, N_ / 128, B_ * HEADS);
        wgemm<true, false, 0, 128><<<grid, 256>>>(
            qkv, qkv + (long)C_ * N_, s, HD, N_, N_, N_,
            HEADS,
            (long)QKV_C * N_, (long)HD * N_,
            (long)QKV_C * N_, (long)HD * N_,
            (long)HEADS * N_ * N_, (long)N_ * N_,
            scale, nullptr, nullptr, 0);
    }

    // 4) Softmax rows
    softmax_kernel<<<B_ * HEADS * N_, 256>>>(s);

    // 5) O[b,h](128,1024) = V @ S^T  (B col-major view of S)
    {
        dim3 grid(N_ / 128, HD / 128, B_ * HEADS);
        wgemm<false, true, 0, 128><<<grid, 256>>>(
            qkv + 2L * C_ * N_, s, o, N_, N_, N_, N_,
            HEADS,
            (long)QKV_C * N_, (long)HD * N_,
            (long)HEADS * N_ * N_, (long)N_ * N_,
            (long)C_ * N_, (long)HD * N_,
            1.0f, nullptr, nullptr, 0);
    }

    // 6) out[b] = proj_w @ o[b] + proj_b + x[b]
    {
        dim3 grid(N_ / 64, C_ / 128, B_);
        wgemm<false, false, 2, 64><<<grid, 256>>>(
            proj_w, o, out, C_, C_, N_, N_,
            1, 0, 0, (long)C_ * N_, 0, (long)C_ * N_, 0,
            1.0f, proj_b, x, (long)C_ * N_);
    }
}

// round 4
// speedup vs baseline: 2.6766x; 1.2430x over previous
#include <cuda_runtime.h>
#include <mma.h>
#include <math.h>
#include <type_traits>

using namespace nvcuda;

// ---------------------------------------------------------------------------
// Shapes (fixed): x (16, 512, 32, 32) -> B=16, C=512, N=1024; heads=4, hd=128
// ---------------------------------------------------------------------------
#define B_   16
#define C_   512
#define N_   1024
#define HEADS 4
#define HD   128
#define GROUPS 32
#define GSIZE (C_ / GROUPS)
#define QKV_C (3 * C_)

// Scratch (device globals — allocation-free per harness rules)
__device__ float g_y  [(size_t)B_ * C_ * N_];
__device__ float g_qkv[(size_t)B_ * QKV_C * N_];
__device__ float g_o  [(size_t)B_ * C_ * N_];

// ---------------------------------------------------------------------------
// GroupNorm
// ---------------------------------------------------------------------------
__global__ void groupnorm_kernel(const float* __restrict__ x,
                                 const float* __restrict__ w,
                                 const float* __restrict__ bias,
                                 float* __restrict__ y)
{
    const int blk = blockIdx.x;
    const int g   = blk % GROUPS;
    const long base = (long)blk * (GSIZE * N_);
    const float* xp = x + base;
    float* yp = y + base;

    const int tid = threadIdx.x;
    float s = 0.f, s2 = 0.f;
    #pragma unroll 8
    for (int i = tid; i < GSIZE * N_; i += 256) {
        float v = xp[i];
        s += v; s2 += v * v;
    }
    __shared__ float rs[32], rs2[32];
    for (int off = 16; off > 0; off >>= 1) {
        s  += __shfl_down_sync(0xffffffffu, s,  off);
        s2 += __shfl_down_sync(0xffffffffu, s2, off);
    }
    if ((tid & 31) == 0) { rs[tid >> 5] = s; rs2[tid >> 5] = s2; }
    __syncthreads();
    if (tid < 32) {
        s  = (tid < 8) ? rs[tid]  : 0.f;
        s2 = (tid < 8) ? rs2[tid] : 0.f;
        for (int off = 4; off > 0; off >>= 1) {
            s  += __shfl_down_sync(0xffffffffu, s,  off);
            s2 += __shfl_down_sync(0xffffffffu, s2, off);
        }
        if (tid == 0) { rs[0] = s; rs2[0] = s2; }
    }
    __syncthreads();
    const float inv_n = 1.0f / (GSIZE * N_);
    const float mean  = rs[0] * inv_n;
    const float var   = rs2[0] * inv_n - mean * mean;
    const float rstd  = rsqrtf(var + 1e-5f);

    const int c0 = g * GSIZE;
    #pragma unroll 4
    for (int i = tid; i < GSIZE * N_; i += 256) {
        int ch = c0 + (i >> 10);
        yp[i] = (xp[i] - mean) * rstd * w[ch] + bias[ch];
    }
}

// ---------------------------------------------------------------------------
// Tile copy GMEM -> SMEM, float4-vectorized, optional tf32 rounding.
// ---------------------------------------------------------------------------
template<int ROWS, int COLS, bool CVT>
__device__ __forceinline__ void tile_copy(float* dst, int sld,
                                          const float* src, long gld, int tid)
{
    constexpr int CV = COLS / 4;
    constexpr int NV = ROWS * CV;
    #pragma unroll
    for (int i = tid; i < NV; i += 256) {
        int r = i / CV, c = i % CV;
        float4 v = *reinterpret_cast<const float4*>(src + (long)r * gld + c * 4);
        if (CVT) {
            v.x = wmma::__float_to_tf32(v.x);
            v.y = wmma::__float_to_tf32(v.y);
            v.z = wmma::__float_to_tf32(v.z);
            v.w = wmma::__float_to_tf32(v.w);
        }
        *reinterpret_cast<float4*>(dst + r * sld + c * 4) = v;
    }
}

// ---------------------------------------------------------------------------
// TF32 wmma GEMM:  C[z] = alpha * op(A[z]) @ op(B[z]) (+ bias[m]) (+ R[z])
// ---------------------------------------------------------------------------
template<bool A_COL, bool B_COL, int EPI, int BN>
__global__ void __launch_bounds__(256)
wgemm(const float* __restrict__ A, const float* __restrict__ B,
      float* __restrict__ C, int K, long lda, long ldb, long ldc,
      int inner,
      long sAo, long sAi, long sBo, long sBi, long sCo, long sCi,
      float alpha, const float* __restrict__ bias,
      const float* __restrict__ R, long sRo)
{
    constexpr int BM = 128, BK = 32, PAD = 4;
    constexpr int ldA = A_COL ? (BM + PAD) : (BK + PAD);
    constexpr int ldB = B_COL ? (BK + PAD) : (BN + PAD);
    constexpr int AsE = A_COL ? BK * (BM + PAD) : BM * (BK + PAD);
    constexpr int BsE = B_COL ? BN * (BK + PAD) : BK * (BN + PAD);
    constexpr int StE = (EPI > 0) ? BM * (BN + PAD) : 1;
    constexpr int SmE = (AsE + BsE > StE) ? (AsE + BsE) : StE;
    constexpr int NT  = BN / 32;
    __shared__ float sm[SmE];
    float* As = sm;
    float* Bs = sm + AsE;

    const int z  = blockIdx.z;
    const int zo = z / inner, zi = z % inner;
    A += zo * sAo + zi * sAi;
    B += zo * sBo + zi * sBi;
    C += zo * sCo + zi * sCi;
    if (EPI == 2) R += zo * sRo;

    const int tid = threadIdx.x;
    const int w   = tid >> 5;
    const int wm  = w >> 1;
    const int wn  = w & 1;
    const int m0  = blockIdx.y * BM;
    const int n0  = blockIdx.x * BN;

    using AL = typename std::conditional<A_COL, wmma::col_major, wmma::row_major>::type;
    using BL = typename std::conditional<B_COL, wmma::col_major, wmma::row_major>::type;

    wmma::fragment<wmma::accumulator, 16, 16, 8, float> acc[2][NT];
    #pragma unroll
    for (int i = 0; i < 2; i++)
        #pragma unroll
        for (int j = 0; j < NT; j++) wmma::fill_fragment(acc[i][j], 0.0f);

    for (int k0 = 0; k0 < K; k0 += BK) {
        if (A_COL) tile_copy<BK, BM, true>(As, ldA, A + (long)k0 * lda + m0, lda, tid);
        else       tile_copy<BM, BK, true>(As, ldA, A + (long)m0 * lda + k0, lda, tid);
        if (B_COL) tile_copy<BN, BK, true>(Bs, ldB, B + (long)n0 * ldb + k0, ldb, tid);
        else       tile_copy<BK, BN, true>(Bs, ldB, B + (long)k0 * ldb + n0, ldb, tid);
        __syncthreads();

        #pragma unroll
        for (int kk = 0; kk < BK; kk += 8) {
            wmma::fragment<wmma::matrix_a, 16, 16, 8, wmma::precision::tf32, AL> af[2];
            wmma::fragment<wmma::matrix_b, 16, 16, 8, wmma::precision::tf32, BL> bf[NT];
            #pragma unroll
            for (int i = 0; i < 2; i++) {
                const float* p = A_COL ? (As + kk * ldA + (wm * 32 + i * 16))
                                       : (As + (wm * 32 + i * 16) * ldA + kk);
                wmma::load_matrix_sync(af[i], p, ldA);
            }
            #pragma unroll
            for (int j = 0; j < NT; j++) {
                int n = wn * (BN / 2) + j * 16;
                const float* p = B_COL ? (Bs + n * ldB + kk)
                                       : (Bs + kk * ldB + n);
                wmma::load_matrix_sync(bf[j], p, ldB);
            }
            #pragma unroll
            for (int i = 0; i < 2; i++)
                #pragma unroll
                for (int j = 0; j < NT; j++)
                    wmma::mma_sync(acc[i][j], af[i], bf[j], acc[i][j]);
        }
        __syncthreads();
    }

    #pragma unroll
    for (int i = 0; i < 2; i++)
        #pragma unroll
        for (int j = 0; j < NT; j++)
            #pragma unroll
            for (int t = 0; t < acc[i][j].num_elements; t++)
                acc[i][j].x[t] *= alpha;

    if (EPI == 0) {
        #pragma unroll
        for (int i = 0; i < 2; i++)
            #pragma unroll
            for (int j = 0; j < NT; j++) {
                int gm = m0 + wm * 32 + i * 16;
                int gn = n0 + wn * (BN / 2) + j * 16;
                wmma::store_matrix_sync(C + (long)gm * ldc + gn, acc[i][j],
                                        (unsigned)ldc, wmma::mem_row_major);
            }
    } else {
        float* St = sm;
        constexpr int ldS = BN + PAD;
        #pragma unroll
        for (int i = 0; i < 2; i++)
            #pragma unroll
            for (int j = 0; j < NT; j++)
                wmma::store_matrix_sync(St + (wm * 32 + i * 16) * ldS
                                           + wn * (BN / 2) + j * 16,
                                        acc[i][j], ldS, wmma::mem_row_major);
        __syncthreads();
        constexpr int CV = BN / 4;
        #pragma unroll
        for (int i = tid; i < BM * CV; i += 256) {
            int r = i / CV, c = i % CV;
            int gm = m0 + r, gn = n0 + c * 4;
            float4 v = *reinterpret_cast<const float4*>(St + r * ldS + c * 4);
            float bv = bias[gm];
            v.x += bv; v.y += bv; v.z += bv; v.w += bv;
            if (EPI == 2) {
                float4 rv = *reinterpret_cast<const float4*>(R + (long)gm * ldc + gn);
                v.x += rv.x; v.y += rv.y; v.z += rv.z; v.w += rv.w;
            }
            *reinterpret_cast<float4*>(C + (long)gm * ldc + gn) = v;
        }
    }
}

// ---------------------------------------------------------------------------
// Fused flash attention.
// Per CTA: 128 queries of one (b, h). Loop over 16 key tiles of 64.
//   S tile : wmma tf32 (Q col-major view [d][q], K row-major view [d][k])
//   softmax: online (m, l) per row in smem
//   O^T    : raw mma.m16n8k8.tf32 accumulators (d = M rows, q = N cols), so
//            the per-query alpha / 1/l scaling indexes by known column layout.
// O written as (C, N) layout: o[d*N + q].
// ---------------------------------------------------------------------------
#define QT 128          // queries per CTA
#define KT 64           // keys per tile
#define QL (QT + 4)     // 132
#define KL (KT + 4)     // 68
#define SL (KT + 4)     // 68

#define OFF_Q  0
#define OFF_K  (OFF_Q + HD * QL)          // 16896
#define OFF_V  (OFF_K + HD * KL)          // 25600
#define OFF_S  (OFF_V + HD * KL)          // 34304
#define OFF_M  (OFF_S + QT * SL)          // 43008
#define OFF_L  (OFF_M + QT)
#define OFF_A  (OFF_L + QT)
#define FLASH_SMEM_FLOATS (OFF_A + QT)    // 43392
#define FLASH_SMEM_BYTES  (FLASH_SMEM_FLOATS * 4)

__device__ __forceinline__ unsigned f2u(float f) { return __float_as_uint(f); }

__device__ __forceinline__ void mma_tf32(float& c0, float& c1, float& c2, float& c3,
                                         unsigned a0, unsigned a1, unsigned a2, unsigned a3,
                                         unsigned b0, unsigned b1)
{
    asm volatile(
        "mma.sync.aligned.m16n8k8.row.col.f32.tf32.tf32.f32 "
        "{%0,%1,%2,%3}, {%4,%5,%6,%7}, {%8,%9}, {%0,%1,%2,%3};\n"
        : "+f"(c0), "+f"(c1), "+f"(c2), "+f"(c3)
        : "r"(a0), "r"(a1), "r"(a2), "r"(a3), "r"(b0), "r"(b1));
}

__global__ void __launch_bounds__(256)
flash_kernel(const float* __restrict__ qkv, float* __restrict__ o)
{
    extern __shared__ float sm[];
    float* Qs = sm + OFF_Q;     // [HD][QL]
    float* Ks = sm + OFF_K;     // [HD][KL]
    float* Vs = sm + OFF_V;     // [HD][KL]
    float* Ss = sm + OFF_S;     // [QT][SL]
    float* Ms = sm + OFF_M;
    float* Ls = sm + OFF_L;
    float* Al = sm + OFF_A;

    const int tid  = threadIdx.x;
    const int w    = tid >> 5;
    const int lane = tid & 31;
    const int g    = lane >> 2;     // groupID
    const int tig  = lane & 3;      // thread-in-group
    const int wm   = w >> 1;        // 0..3
    const int wn   = w & 1;         // 0..1

    const int q0 = blockIdx.x * QT;
    const int bh = blockIdx.y;
    const long base = ((long)(bh >> 2) * QKV_C + (long)(bh & 3) * HD) * N_;
    const float* Qg = qkv + base;
    const float* Kg = qkv + base + (long)C_ * N_;
    const float* Vg = qkv + base + 2L * (long)C_ * N_;
    float* Og = o + ((long)(bh >> 2) * C_ + (long)(bh & 3) * HD) * N_ + q0;

    const float scale = 0.08838834764831845f;

    // --- load Q tile [128 d][128 q] (natural layout, float4) ---
    #pragma unroll
    for (int i = tid; i < HD * (QT / 4); i += 256) {
        int r = i >> 5, c = i & 31;
        float4 v = *reinterpret_cast<const float4*>(Qg + (long)r * N_ + q0 + c * 4);
        *reinterpret_cast<float4*>(Qs + r * QL + c * 4) = v;
    }
    if (tid < QT) { Ms[tid] = -1e30f; Ls[tid] = 0.f; }

    // O^T accumulators: M=HD (d), N=QT (q). Warp tile: 32 d x 64 q.
    float oc[2][8][4];
    #pragma unroll
    for (int i = 0; i < 2; i++)
        #pragma unroll
        for (int j = 0; j < 8; j++)
            #pragma unroll
            for (int t = 0; t < 4; t++) oc[i][j][t] = 0.f;

    for (int kt = 0; kt < N_ / KT; kt++) {
        const int k0 = kt * KT;
        __syncthreads();                       // prev iter done with Ks/Vs/Ss

        // --- load K, V tiles [128 d][64 k] ---
        #pragma unroll
        for (int i = tid; i < HD * (KT / 4); i += 256) {
            int r = i >> 4, c = i & 15;
            float4 kv = *reinterpret_cast<const float4*>(Kg + (long)r * N_ + k0 + c * 4);
            float4 vv = *reinterpret_cast<const float4*>(Vg + (long)r * N_ + k0 + c * 4);
            *reinterpret_cast<float4*>(Ks + r * KL + c * 4) = kv;
            *reinterpret_cast<float4*>(Vs + r * KL + c * 4) = vv;
        }
        __syncthreads();

        // --- S = Q^T K : m=128(q), n=64(k), k=128(d), wmma tf32 ---
        {
            wmma::fragment<wmma::accumulator, 16, 16, 8, float> sacc[2][2];
            #pragma unroll
            for (int i = 0; i < 2; i++)
                #pragma unroll
                for (int j = 0; j < 2; j++) wmma::fill_fragment(sacc[i][j], 0.0f);

            #pragma unroll
            for (int kk = 0; kk < HD; kk += 8) {
                wmma::fragment<wmma::matrix_a, 16, 16, 8, wmma::precision::tf32,
                               wmma::col_major> af[2];
                wmma::fragment<wmma::matrix_b, 16, 16, 8, wmma::precision::tf32,
                               wmma::row_major> bf[2];
                #pragma unroll
                for (int i = 0; i < 2; i++)
                    wmma::load_matrix_sync(af[i], Qs + kk * QL + wm * 32 + i * 16, QL);
                #pragma unroll
                for (int j = 0; j < 2; j++)
                    wmma::load_matrix_sync(bf[j], Ks + kk * KL + wn * 32 + j * 16, KL);
                #pragma unroll
                for (int i = 0; i < 2; i++)
                    #pragma unroll
                    for (int j = 0; j < 2; j++)
                        wmma::mma_sync(sacc[i][j], af[i], bf[j], sacc[i][j]);
            }
            #pragma unroll
            for (int i = 0; i < 2; i++)
                #pragma unroll
                for (int j = 0; j < 2; j++) {
                    #pragma unroll
                    for (int t = 0; t < sacc[i][j].num_elements; t++)
                        sacc[i][j].x[t] *= scale;
                    wmma::store_matrix_sync(Ss + (wm * 32 + i * 16) * SL + wn * 32 + j * 16,
                                            sacc[i][j], SL, wmma::mem_row_major);
                }
        }
        __syncthreads();

        // --- online softmax on Ss rows; 2 threads per row, 32 cols each ---
        {
            const int r    = tid >> 1;
            const int half = tid & 1;
            float* row = Ss + r * SL + half * 32;
            float4 v[8];
            float mx = -1e30f;
            #pragma unroll
            for (int i = 0; i < 8; i++) {
                v[i] = *reinterpret_cast<const float4*>(row + i * 4);
                mx = fmaxf(mx, fmaxf(fmaxf(v[i].x, v[i].y), fmaxf(v[i].z, v[i].w)));
            }
            mx = fmaxf(mx, __shfl_xor_sync(0xffffffffu, mx, 1));
            const float mo = Ms[r];
            const float mn = fmaxf(mo, mx);
            const float alpha = __expf(mo - mn);
            float s = 0.f;
            #pragma unroll
            for (int i = 0; i < 8; i++) {
                v[i].x = __expf(v[i].x - mn); v[i].y = __expf(v[i].y - mn);
                v[i].z = __expf(v[i].z - mn); v[i].w = __expf(v[i].w - mn);
                s += v[i].x + v[i].y + v[i].z + v[i].w;
                *reinterpret_cast<float4*>(row + i * 4) = v[i];
            }
            s += __shfl_xor_sync(0xffffffffu, s, 1);
            if (half == 0) {
                Ms[r] = mn;
                Ls[r] = Ls[r] * alpha + s;
                Al[r] = alpha;
            }
        }
        __syncthreads();

        // --- rescale O by alpha (per column q), then O^T += V @ P^T ---
        {
            const int qb = wn * 64;
            #pragma unroll
            for (int j = 0; j < 8; j++) {
                const float aE = Al[qb + j * 8 + 2 * tig];
                const float aO = Al[qb + j * 8 + 2 * tig + 1];
                #pragma unroll
                for (int i = 0; i < 2; i++) {
                    oc[i][j][0] *= aE; oc[i][j][1] *= aO;
                    oc[i][j][2] *= aE; oc[i][j][3] *= aO;
                }
            }
            #pragma unroll
            for (int kk = 0; kk < KT; kk += 8) {
                unsigned b0[8], b1[8];
                #pragma unroll
                for (int j = 0; j < 8; j++) {
                    const float* pr = Ss + (qb + j * 8 + g) * SL + kk;
                    b0[j] = f2u(pr[tig]);
                    b1[j] = f2u(pr[tig + 4]);
                }
                #pragma unroll
                for (int i = 0; i < 2; i++) {
                    const int dr = wm * 32 + i * 16;
                    const float* vr0 = Vs + (dr + g) * KL + kk;
                    const float* vr1 = Vs + (dr + g + 8) * KL + kk;
                    unsigned a0 = f2u(vr0[tig]);
                    unsigned a1 = f2u(vr1[tig]);
                    unsigned a2 = f2u(vr0[tig + 4]);
                    unsigned a3 = f2u(vr1[tig + 4]);
                    #pragma unroll
                    for (int j = 0; j < 8; j++)
                        mma_tf32(oc[i][j][0], oc[i][j][1], oc[i][j][2], oc[i][j][3],
                                 a0, a1, a2, a3, b0[j], b1[j]);
                }
            }
        }
    }

    // --- final: divide by l (per column q), store O^T -> o[d][q] ---
    {
        const int qb = wn * 64;
        #pragma unroll
        for (int j = 0; j < 8; j++) {
            const int qc = qb + j * 8 + 2 * tig;
            const float iE = 1.0f / Ls[qc];
            const float iO = 1.0f / Ls[qc + 1];
            #pragma unroll
            for (int i = 0; i < 2; i++) {
                const int dr = wm * 32 + i * 16;
                float2 lo = make_float2(oc[i][j][0] * iE, oc[i][j][1] * iO);
                float2 hi = make_float2(oc[i][j][2] * iE, oc[i][j][3] * iO);
                *reinterpret_cast<float2*>(Og + (long)(dr + g) * N_ + qc) = lo;
                *reinterpret_cast<float2*>(Og + (long)(dr + g + 8) * N_ + qc) = hi;
            }
        }
    }
}

// ---------------------------------------------------------------------------
// Launch
// ---------------------------------------------------------------------------
extern "C" void kernel_launch(void* const* d_in, const int* in_sizes, int n_in,
                              void* d_out, int out_size)
{
    const float* x      = (const float*)d_in[0];
    const float* norm_w = (const float*)d_in[1];
    const float* norm_b = (const float*)d_in[2];
    const float* qkv_w  = (const float*)d_in[3];
    const float* qkv_b  = (const float*)d_in[4];
    const float* proj_w = (const float*)d_in[5];
    const float* proj_b = (const float*)d_in[6];
    float* out          = (float*)d_out;

    float *y, *qkv, *o;
    cudaGetSymbolAddress((void**)&y,   g_y);
    cudaGetSymbolAddress((void**)&qkv, g_qkv);
    cudaGetSymbolAddress((void**)&o,   g_o);

    // Idempotent, deterministic; not a stream op so safe under graph capture.
    cudaFuncSetAttribute(flash_kernel,
                         cudaFuncAttributeMaxDynamicSharedMemorySize,
                         FLASH_SMEM_BYTES);

    // 1) GroupNorm
    groupnorm_kernel<<<B_ * GROUPS, 256>>>(x, norm_w, norm_b, y);

    // 2) QKV: qkv[b](1536,1024) = qkv_w(1536,512) @ y[b] + qkv_b
    {
        dim3 grid(N_ / 64, QKV_C / 128, B_);
        wgemm<false, false, 1, 64><<<grid, 256>>>(
            qkv_w, y, qkv, C_, C_, N_, N_,
            1, 0, 0, (long)C_ * N_, 0, (long)QKV_C * N_, 0,
            1.0f, qkv_b, nullptr, 0);
    }

    // 3) Fused attention -> o (B, C, N)
    {
        dim3 grid(N_ / QT, B_ * HEADS);
        flash_kernel<<<grid, 256, FLASH_SMEM_BYTES>>>(qkv, o);
    }

    // 4) out[b] = proj_w @ o[b] + proj_b + x[b]
    {
        dim3 grid(N_ / 64, C_ / 128, B_);
        wgemm<false, false, 2, 64><<<grid, 256>>>(
            proj_w, o, out, C_, C_, N_, N_,
            1, 0, 0, (long)C_ * N_, 0, (long)C_ * N_, 0,
            1.0f, proj_b, x, (long)C_ * N_);
    }
}

// round 5
// speedup vs baseline: 2.7251x; 1.0181x over previous
#include <cuda_runtime.h>
#include <mma.h>
#include <math.h>

using namespace nvcuda;

// ---------------------------------------------------------------------------
// Shapes (fixed): x (16, 512, 32, 32) -> B=16, C=512, N=1024; heads=4, hd=128
// ---------------------------------------------------------------------------
#define B_   16
#define C_   512
#define N_   1024
#define HEADS 4
#define HD   128
#define GROUPS 32
#define GSIZE (C_ / GROUPS)
#define QKV_C (3 * C_)

// Scratch (device globals — allocation-free per harness rules)
__device__ float g_y  [(size_t)B_ * C_ * N_];
__device__ float g_qkv[(size_t)B_ * QKV_C * N_];
__device__ float g_o  [(size_t)B_ * C_ * N_];

// ---------------------------------------------------------------------------
// cp.async helpers
// ---------------------------------------------------------------------------
__device__ __forceinline__ void cp_async16(void* smem_dst, const void* gmem_src)
{
    unsigned s = (unsigned)__cvta_generic_to_shared(smem_dst);
    asm volatile("cp.async.cg.shared.global [%0], [%1], 16;\n" :: "r"(s), "l"(gmem_src));
}
__device__ __forceinline__ void cp_commit() { asm volatile("cp.async.commit_group;\n"); }
template<int N> __device__ __forceinline__ void cp_wait()
{ asm volatile("cp.async.wait_group %0;\n" :: "n"(N)); }

// ---------------------------------------------------------------------------
// GroupNorm
// ---------------------------------------------------------------------------
__global__ void groupnorm_kernel(const float* __restrict__ x,
                                 const float* __restrict__ w,
                                 const float* __restrict__ bias,
                                 float* __restrict__ y)
{
    const int blk = blockIdx.x;
    const int g   = blk % GROUPS;
    const long base = (long)blk * (GSIZE * N_);
    const float* xp = x + base;
    float* yp = y + base;

    const int tid = threadIdx.x;
    float s = 0.f, s2 = 0.f;
    #pragma unroll 8
    for (int i = tid; i < GSIZE * N_; i += 256) {
        float v = xp[i];
        s += v; s2 += v * v;
    }
    __shared__ float rs[32], rs2[32];
    for (int off = 16; off > 0; off >>= 1) {
        s  += __shfl_down_sync(0xffffffffu, s,  off);
        s2 += __shfl_down_sync(0xffffffffu, s2, off);
    }
    if ((tid & 31) == 0) { rs[tid >> 5] = s; rs2[tid >> 5] = s2; }
    __syncthreads();
    if (tid < 32) {
        s  = (tid < 8) ? rs[tid]  : 0.f;
        s2 = (tid < 8) ? rs2[tid] : 0.f;
        for (int off = 4; off > 0; off >>= 1) {
            s  += __shfl_down_sync(0xffffffffu, s,  off);
            s2 += __shfl_down_sync(0xffffffffu, s2, off);
        }
        if (tid == 0) { rs[0] = s; rs2[0] = s2; }
    }
    __syncthreads();
    const float inv_n = 1.0f / (GSIZE * N_);
    const float mean  = rs[0] * inv_n;
    const float var   = rs2[0] * inv_n - mean * mean;
    const float rstd  = rsqrtf(var + 1e-5f);

    const int c0 = g * GSIZE;
    #pragma unroll 4
    for (int i = tid; i < GSIZE * N_; i += 256) {
        int ch = c0 + (i >> 10);
        yp[i] = (xp[i] - mean) * rstd * w[ch] + bias[ch];
    }
}

// ---------------------------------------------------------------------------
// 2-stage cp.async TF32 wmma GEMM (row-major A and B; the only layout used):
//   C[z] = A(MxK) @ B[z](KxN) + bias[m] (+ R[z])
// BM=128, BN=64, BK=64. 8 warps (4m x 2n), warp tile 32x32.
// ---------------------------------------------------------------------------
#define GBM 128
#define GBN 64
#define GBK 64
#define GLDA (GBK + 4)                 // 68 floats (272B, 16B-multiple)
#define GLDB (GBN + 4)                 // 68
#define GSTG (GBM * GLDA + GBK * GLDB) // 13056 floats per stage
#define GSM_FLOATS (2 * GSTG)          // 26112 (104.4 KB); epilogue staging reuses
#define GSM_BYTES (GSM_FLOATS * 4)

template<int EPI>   // 1: +bias   2: +bias +residual
__global__ void __launch_bounds__(256)
wgemm2(const float* __restrict__ A, const float* __restrict__ B,
       float* __restrict__ C, int M, int K, int Nn,
       long sB, long sC, const float* __restrict__ bias,
       const float* __restrict__ R, long sR)
{
    extern __shared__ float sm[];
    const int z = blockIdx.z;
    B += (long)z * sB;
    C += (long)z * sC;
    if (EPI == 2) R += (long)z * sR;

    const int tid = threadIdx.x;
    const int w   = tid >> 5;
    const int wm  = w >> 1;
    const int wn  = w & 1;
    const int m0  = blockIdx.y * GBM;
    const int n0  = blockIdx.x * GBN;

    // per-thread copy coords (16 float4 per row for both tiles)
    const int ar = tid >> 4, ac = (tid & 15) * 4;   // A: 2048 f4, 8/thread
    const int br = tid >> 4, bc = (tid & 15) * 4;   // B: 1024 f4, 4/thread

    auto issue_tile = [&](int k0, int st) {
        float* As = sm + st * GSTG;
        float* Bs = As + GBM * GLDA;
        #pragma unroll
        for (int it = 0; it < 8; it++) {
            int r = ar + it * 16;
            cp_async16(As + r * GLDA + ac, A + (long)(m0 + r) * K + k0 + ac);
        }
        #pragma unroll
        for (int it = 0; it < 4; it++) {
            int r = br + it * 16;
            cp_async16(Bs + r * GLDB + bc, B + (long)(k0 + r) * Nn + n0 + bc);
        }
        cp_commit();
    };

    wmma::fragment<wmma::accumulator, 16, 16, 8, float> acc[2][2];
    #pragma unroll
    for (int i = 0; i < 2; i++)
        #pragma unroll
        for (int j = 0; j < 2; j++) wmma::fill_fragment(acc[i][j], 0.0f);

    const int tiles = K / GBK;
    issue_tile(0, 0);

    for (int t = 0; t < tiles; t++) {
        if (t + 1 < tiles) { issue_tile((t + 1) * GBK, (t + 1) & 1); cp_wait<1>(); }
        else               { cp_wait<0>(); }
        __syncthreads();

        const float* As = sm + (t & 1) * GSTG;
        const float* Bs = As + GBM * GLDA;
        #pragma unroll
        for (int kk = 0; kk < GBK; kk += 8) {
            wmma::fragment<wmma::matrix_a, 16, 16, 8, wmma::precision::tf32,
                           wmma::row_major> af[2];
            wmma::fragment<wmma::matrix_b, 16, 16, 8, wmma::precision::tf32,
                           wmma::row_major> bf[2];
            #pragma unroll
            for (int i = 0; i < 2; i++)
                wmma::load_matrix_sync(af[i], As + (wm * 32 + i * 16) * GLDA + kk, GLDA);
            #pragma unroll
            for (int j = 0; j < 2; j++)
                wmma::load_matrix_sync(bf[j], Bs + kk * GLDB + wn * 32 + j * 16, GLDB);
            #pragma unroll
            for (int i = 0; i < 2; i++)
                #pragma unroll
                for (int j = 0; j < 2; j++)
                    wmma::mma_sync(acc[i][j], af[i], bf[j], acc[i][j]);
        }
        __syncthreads();   // stage (t&1) will be overwritten at t+1's issue
    }

    // epilogue: stage through smem (free now), add bias / residual, store
    float* St = sm;
    constexpr int ldS = GBN + 4;
    #pragma unroll
    for (int i = 0; i < 2; i++)
        #pragma unroll
        for (int j = 0; j < 2; j++)
            wmma::store_matrix_sync(St + (wm * 32 + i * 16) * ldS + wn * 32 + j * 16,
                                    acc[i][j], ldS, wmma::mem_row_major);
    __syncthreads();
    #pragma unroll
    for (int i = tid; i < GBM * (GBN / 4); i += 256) {
        int r = i >> 4, c = (i & 15) * 4;
        int gm = m0 + r, gn = n0 + c;
        float4 v = *reinterpret_cast<const float4*>(St + r * ldS + c);
        float bv = bias[gm];
        v.x += bv; v.y += bv; v.z += bv; v.w += bv;
        if (EPI == 2) {
            float4 rv = *reinterpret_cast<const float4*>(R + (long)gm * Nn + gn);
            v.x += rv.x; v.y += rv.y; v.z += rv.z; v.w += rv.w;
        }
        *reinterpret_cast<float4*>(C + (long)gm * Nn + gn) = v;
    }
}

// ---------------------------------------------------------------------------
// Fused flash attention (as R4) + register prefetch of next K/V tile.
// ---------------------------------------------------------------------------
#define QT 128
#define KT 64
#define QL (QT + 4)
#define KL (KT + 4)
#define SL (KT + 4)

#define OFF_Q  0
#define OFF_K  (OFF_Q + HD * QL)
#define OFF_V  (OFF_K + HD * KL)
#define OFF_S  (OFF_V + HD * KL)
#define OFF_M  (OFF_S + QT * SL)
#define OFF_L  (OFF_M + QT)
#define OFF_A  (OFF_L + QT)
#define FLASH_SMEM_FLOATS (OFF_A + QT)
#define FLASH_SMEM_BYTES  (FLASH_SMEM_FLOATS * 4)

__device__ __forceinline__ unsigned f2u(float f) { return __float_as_uint(f); }

__device__ __forceinline__ void mma_tf32(float& c0, float& c1, float& c2, float& c3,
                                         unsigned a0, unsigned a1, unsigned a2, unsigned a3,
                                         unsigned b0, unsigned b1)
{
    asm volatile(
        "mma.sync.aligned.m16n8k8.row.col.f32.tf32.tf32.f32 "
        "{%0,%1,%2,%3}, {%4,%5,%6,%7}, {%8,%9}, {%0,%1,%2,%3};\n"
        : "+f"(c0), "+f"(c1), "+f"(c2), "+f"(c3)
        : "r"(a0), "r"(a1), "r"(a2), "r"(a3), "r"(b0), "r"(b1));
}

__global__ void __launch_bounds__(256)
flash_kernel(const float* __restrict__ qkv, float* __restrict__ o)
{
    extern __shared__ float sm[];
    float* Qs = sm + OFF_Q;
    float* Ks = sm + OFF_K;
    float* Vs = sm + OFF_V;
    float* Ss = sm + OFF_S;
    float* Ms = sm + OFF_M;
    float* Ls = sm + OFF_L;
    float* Al = sm + OFF_A;

    const int tid  = threadIdx.x;
    const int w    = tid >> 5;
    const int lane = tid & 31;
    const int g    = lane >> 2;
    const int tig  = lane & 3;
    const int wm   = w >> 1;
    const int wn   = w & 1;

    const int q0 = blockIdx.x * QT;
    const int bh = blockIdx.y;
    const long base = ((long)(bh >> 2) * QKV_C + (long)(bh & 3) * HD) * N_;
    const float* Qg = qkv + base;
    const float* Kg = qkv + base + (long)C_ * N_;
    const float* Vg = qkv + base + 2L * (long)C_ * N_;
    float* Og = o + ((long)(bh >> 2) * C_ + (long)(bh & 3) * HD) * N_ + q0;

    const float scale = 0.08838834764831845f;

    // Q tile [128 d][128 q]
    #pragma unroll
    for (int i = tid; i < HD * (QT / 4); i += 256) {
        int r = i >> 5, c = i & 31;
        float4 v = *reinterpret_cast<const float4*>(Qg + (long)r * N_ + q0 + c * 4);
        *reinterpret_cast<float4*>(Qs + r * QL + c * 4) = v;
    }
    if (tid < QT) { Ms[tid] = -1e30f; Ls[tid] = 0.f; }

    // prefetch registers: per thread 8 K-f4 + 8 V-f4 (rows tid>>4 + it*16)
    const int pr = tid >> 4, pc = (tid & 15) * 4;
    float4 pk[8], pv[8];
    #pragma unroll
    for (int it = 0; it < 8; it++) {
        int r = pr + it * 16;
        pk[it] = *reinterpret_cast<const float4*>(Kg + (long)r * N_ + pc);
        pv[it] = *reinterpret_cast<const float4*>(Vg + (long)r * N_ + pc);
    }

    float oc[2][8][4];
    #pragma unroll
    for (int i = 0; i < 2; i++)
        #pragma unroll
        for (int j = 0; j < 8; j++)
            #pragma unroll
            for (int t = 0; t < 4; t++) oc[i][j][t] = 0.f;

    for (int kt = 0; kt < N_ / KT; kt++) {
        __syncthreads();                       // prev iter done with Ks/Vs/Ss

        // store prefetched K/V tile
        #pragma unroll
        for (int it = 0; it < 8; it++) {
            int r = pr + it * 16;
            *reinterpret_cast<float4*>(Ks + r * KL + pc) = pk[it];
            *reinterpret_cast<float4*>(Vs + r * KL + pc) = pv[it];
        }
        // issue next tile's loads (consumed next iteration)
        if (kt + 1 < N_ / KT) {
            const int k0n = (kt + 1) * KT;
            #pragma unroll
            for (int it = 0; it < 8; it++) {
                int r = pr + it * 16;
                pk[it] = *reinterpret_cast<const float4*>(Kg + (long)r * N_ + k0n + pc);
                pv[it] = *reinterpret_cast<const float4*>(Vg + (long)r * N_ + k0n + pc);
            }
        }
        __syncthreads();

        // S = Q^T K
        {
            wmma::fragment<wmma::accumulator, 16, 16, 8, float> sacc[2][2];
            #pragma unroll
            for (int i = 0; i < 2; i++)
                #pragma unroll
                for (int j = 0; j < 2; j++) wmma::fill_fragment(sacc[i][j], 0.0f);

            #pragma unroll
            for (int kk = 0; kk < HD; kk += 8) {
                wmma::fragment<wmma::matrix_a, 16, 16, 8, wmma::precision::tf32,
                               wmma::col_major> af[2];
                wmma::fragment<wmma::matrix_b, 16, 16, 8, wmma::precision::tf32,
                               wmma::row_major> bf[2];
                #pragma unroll
                for (int i = 0; i < 2; i++)
                    wmma::load_matrix_sync(af[i], Qs + kk * QL + wm * 32 + i * 16, QL);
                #pragma unroll
                for (int j = 0; j < 2; j++)
                    wmma::load_matrix_sync(bf[j], Ks + kk * KL + wn * 32 + j * 16, KL);
                #pragma unroll
                for (int i = 0; i < 2; i++)
                    #pragma unroll
                    for (int j = 0; j < 2; j++)
                        wmma::mma_sync(sacc[i][j], af[i], bf[j], sacc[i][j]);
            }
            #pragma unroll
            for (int i = 0; i < 2; i++)
                #pragma unroll
                for (int j = 0; j < 2; j++) {
                    #pragma unroll
                    for (int t = 0; t < sacc[i][j].num_elements; t++)
                        sacc[i][j].x[t] *= scale;
                    wmma::store_matrix_sync(Ss + (wm * 32 + i * 16) * SL + wn * 32 + j * 16,
                                            sacc[i][j], SL, wmma::mem_row_major);
                }
        }
        __syncthreads();

        // online softmax (2 threads per row)
        {
            const int r    = tid >> 1;
            const int half = tid & 1;
            float* row = Ss + r * SL + half * 32;
            float4 v[8];
            float mx = -1e30f;
            #pragma unroll
            for (int i = 0; i < 8; i++) {
                v[i] = *reinterpret_cast<const float4*>(row + i * 4);
                mx = fmaxf(mx, fmaxf(fmaxf(v[i].x, v[i].y), fmaxf(v[i].z, v[i].w)));
            }
            mx = fmaxf(mx, __shfl_xor_sync(0xffffffffu, mx, 1));
            const float mo = Ms[r];
            const float mn = fmaxf(mo, mx);
            const float alpha = __expf(mo - mn);
            float s = 0.f;
            #pragma unroll
            for (int i = 0; i < 8; i++) {
                v[i].x = __expf(v[i].x - mn); v[i].y = __expf(v[i].y - mn);
                v[i].z = __expf(v[i].z - mn); v[i].w = __expf(v[i].w - mn);
                s += v[i].x + v[i].y + v[i].z + v[i].w;
                *reinterpret_cast<float4*>(row + i * 4) = v[i];
            }
            s += __shfl_xor_sync(0xffffffffu, s, 1);
            if (half == 0) {
                Ms[r] = mn;
                Ls[r] = Ls[r] * alpha + s;
                Al[r] = alpha;
            }
        }
        __syncthreads();

        // rescale O, then O^T += V @ P^T
        {
            const int qb = wn * 64;
            #pragma unroll
            for (int j = 0; j < 8; j++) {
                const float aE = Al[qb + j * 8 + 2 * tig];
                const float aO = Al[qb + j * 8 + 2 * tig + 1];
                #pragma unroll
                for (int i = 0; i < 2; i++) {
                    oc[i][j][0] *= aE; oc[i][j][1] *= aO;
                    oc[i][j][2] *= aE; oc[i][j][3] *= aO;
                }
            }
            #pragma unroll
            for (int kk = 0; kk < KT; kk += 8) {
                unsigned b0[8], b1[8];
                #pragma unroll
                for (int j = 0; j < 8; j++) {
                    const float* prow = Ss + (qb + j * 8 + g) * SL + kk;
                    b0[j] = f2u(prow[tig]);
                    b1[j] = f2u(prow[tig + 4]);
                }
                #pragma unroll
                for (int i = 0; i < 2; i++) {
                    const int dr = wm * 32 + i * 16;
                    const float* vr0 = Vs + (dr + g) * KL + kk;
                    const float* vr1 = Vs + (dr + g + 8) * KL + kk;
                    unsigned a0 = f2u(vr0[tig]);
                    unsigned a1 = f2u(vr1[tig]);
                    unsigned a2 = f2u(vr0[tig + 4]);
                    unsigned a3 = f2u(vr1[tig + 4]);
                    #pragma unroll
                    for (int j = 0; j < 8; j++)
                        mma_tf32(oc[i][j][0], oc[i][j][1], oc[i][j][2], oc[i][j][3],
                                 a0, a1, a2, a3, b0[j], b1[j]);
                }
            }
        }
    }

    // final: /l, store O^T
    {
        const int qb = wn * 64;
        #pragma unroll
        for (int j = 0; j < 8; j++) {
            const int qc = qb + j * 8 + 2 * tig;
            const float iE = 1.0f / Ls[qc];
            const float iO = 1.0f / Ls[qc + 1];
            #pragma unroll
            for (int i = 0; i < 2; i++) {
                const int dr = wm * 32 + i * 16;
                float2 lo = make_float2(oc[i][j][0] * iE, oc[i][j][1] * iO);
                float2 hi = make_float2(oc[i][j][2] * iE, oc[i][j][3] * iO);
                *reinterpret_cast<float2*>(Og + (long)(dr + g) * N_ + qc) = lo;
                *reinterpret_cast<float2*>(Og + (long)(dr + g + 8) * N_ + qc) = hi;
            }
        }
    }
}

// ---------------------------------------------------------------------------
// Launch
// ---------------------------------------------------------------------------
extern "C" void kernel_launch(void* const* d_in, const int* in_sizes, int n_in,
                              void* d_out, int out_size)
{
    const float* x      = (const float*)d_in[0];
    const float* norm_w = (const float*)d_in[1];
    const float* norm_b = (const float*)d_in[2];
    const float* qkv_w  = (const float*)d_in[3];
    const float* qkv_b  = (const float*)d_in[4];
    const float* proj_w = (const float*)d_in[5];
    const float* proj_b = (const float*)d_in[6];
    float* out          = (float*)d_out;

    float *y, *qkv, *o;
    cudaGetSymbolAddress((void**)&y,   g_y);
    cudaGetSymbolAddress((void**)&qkv, g_qkv);
    cudaGetSymbolAddress((void**)&o,   g_o);

    // Idempotent attribute setup (not stream ops; safe under graph capture)
    cudaFuncSetAttribute(flash_kernel,
                         cudaFuncAttributeMaxDynamicSharedMemorySize,
                         FLASH_SMEM_BYTES);
    cudaFuncSetAttribute(wgemm2<1>,
                         cudaFuncAttributeMaxDynamicSharedMemorySize, GSM_BYTES);
    cudaFuncSetAttribute(wgemm2<2>,
                         cudaFuncAttributeMaxDynamicSharedMemorySize, GSM_BYTES);

    // 1) GroupNorm
    groupnorm_kernel<<<B_ * GROUPS, 256>>>(x, norm_w, norm_b, y);

    // 2) QKV: qkv[b](1536,1024) = qkv_w @ y[b] + qkv_b
    {
        dim3 grid(N_ / GBN, QKV_C / GBM, B_);
        wgemm2<1><<<grid, 256, GSM_BYTES>>>(
            qkv_w, y, qkv, QKV_C, C_, N_,
            (long)C_ * N_, (long)QKV_C * N_, qkv_b, nullptr, 0);
    }

    // 3) Fused attention -> o (B, C, N)
    {
        dim3 grid(N_ / QT, B_ * HEADS);
        flash_kernel<<<grid, 256, FLASH_SMEM_BYTES>>>(qkv, o);
    }

    // 4) out[b] = proj_w @ o[b] + proj_b + x[b]
    {
        dim3 grid(N_ / GBN, C_ / GBM, B_);
        wgemm2<2><<<grid, 256, GSM_BYTES>>>(
            proj_w, o, out, C_, C_, N_,
            (long)C_ * N_, (long)C_ * N_, proj_b, x, (long)C_ * N_);
    }
}

// round 7
// speedup vs baseline: 2.8376x; 1.0413x over previous
#include <cuda_runtime.h>
#include <mma.h>
#include <math.h>

using namespace nvcuda;

// ---------------------------------------------------------------------------
// Shapes (fixed): x (16, 512, 32, 32) -> B=16, C=512, N=1024; heads=4, hd=128
// ---------------------------------------------------------------------------
#define B_   16
#define C_   512
#define N_   1024
#define HEADS 4
#define HD   128
#define GROUPS 32
#define GSIZE (C_ / GROUPS)
#define QKV_C (3 * C_)

// Scratch (device globals — allocation-free per harness rules)
__device__ float g_y  [(size_t)B_ * C_ * N_];
__device__ float g_qkv[(size_t)B_ * QKV_C * N_];
__device__ float g_o  [(size_t)B_ * C_ * N_];

// ---------------------------------------------------------------------------
// cp.async helpers
// ---------------------------------------------------------------------------
__device__ __forceinline__ void cp_async16(void* smem_dst, const void* gmem_src)
{
    unsigned s = (unsigned)__cvta_generic_to_shared(smem_dst);
    asm volatile("cp.async.cg.shared.global [%0], [%1], 16;\n" :: "r"(s), "l"(gmem_src));
}
__device__ __forceinline__ void cp_commit() { asm volatile("cp.async.commit_group;\n"); }
template<int N> __device__ __forceinline__ void cp_wait()
{ asm volatile("cp.async.wait_group %0;\n" :: "n"(N)); }

// ---------------------------------------------------------------------------
// GroupNorm
// ---------------------------------------------------------------------------
__global__ void groupnorm_kernel(const float* __restrict__ x,
                                 const float* __restrict__ w,
                                 const float* __restrict__ bias,
                                 float* __restrict__ y)
{
    const int blk = blockIdx.x;
    const int g   = blk % GROUPS;
    const long base = (long)blk * (GSIZE * N_);
    const float* xp = x + base;
    float* yp = y + base;

    const int tid = threadIdx.x;
    float s = 0.f, s2 = 0.f;
    #pragma unroll 8
    for (int i = tid; i < GSIZE * N_; i += 256) {
        float v = xp[i];
        s += v; s2 += v * v;
    }
    __shared__ float rs[32], rs2[32];
    for (int off = 16; off > 0; off >>= 1) {
        s  += __shfl_down_sync(0xffffffffu, s,  off);
        s2 += __shfl_down_sync(0xffffffffu, s2, off);
    }
    if ((tid & 31) == 0) { rs[tid >> 5] = s; rs2[tid >> 5] = s2; }
    __syncthreads();
    if (tid < 32) {
        s  = (tid < 8) ? rs[tid]  : 0.f;
        s2 = (tid < 8) ? rs2[tid] : 0.f;
        for (int off = 4; off > 0; off >>= 1) {
            s  += __shfl_down_sync(0xffffffffu, s,  off);
            s2 += __shfl_down_sync(0xffffffffu, s2, off);
        }
        if (tid == 0) { rs[0] = s; rs2[0] = s2; }
    }
    __syncthreads();
    const float inv_n = 1.0f / (GSIZE * N_);
    const float mean  = rs[0] * inv_n;
    const float var   = rs2[0] * inv_n - mean * mean;
    const float rstd  = rsqrtf(var + 1e-5f);

    const int c0 = g * GSIZE;
    #pragma unroll 4
    for (int i = tid; i < GSIZE * N_; i += 256) {
        int ch = c0 + (i >> 10);
        yp[i] = (xp[i] - mean) * rstd * w[ch] + bias[ch];
    }
}

// ---------------------------------------------------------------------------
// 2-stage cp.async TF32 wmma GEMM, wide warp tiles:
//   C[z] = A(MxK) @ B[z](KxN) + bias[m] (+ R[z])
// BM=128, BN=128, BK=32. 8 warps as 2m x 4n; warp tile 64x32 = 4x2 frags
// (8 independent HMMA accumulator chains per warp).
// ---------------------------------------------------------------------------
#define WBM 128
#define WBN 128
#define WBK 32
#define WLDA (WBK + 4)                   // 36
#define WLDB (WBN + 4)                   // 132
#define WSTG (WBM * WLDA + WBK * WLDB)   // 4608 + 4224 = 8832 floats / stage
#define WSM_FLOATS (2 * WSTG)            // 17664 (70.7 KB)
#define WSM_BYTES (WSM_FLOATS * 4)

template<int EPI>   // 1: +bias   2: +bias +residual
__global__ void __launch_bounds__(256, 2)
wgemm3(const float* __restrict__ A, const float* __restrict__ B,
       float* __restrict__ C, int M, int K, int Nn,
       long sB, long sC, const float* __restrict__ bias,
       const float* __restrict__ R, long sR)
{
    extern __shared__ float sm[];
    const int z = blockIdx.z;
    B += (long)z * sB;
    C += (long)z * sC;
    if (EPI == 2) R += (long)z * sR;

    const int tid = threadIdx.x;
    const int w   = tid >> 5;
    const int wm  = w >> 2;              // 0..1  (64-row slab)
    const int wn  = w & 3;               // 0..3  (32-col slab)
    const int m0  = blockIdx.y * WBM;
    const int n0  = blockIdx.x * WBN;

    // copy coords: A tile 128x32 (8 f4/row), B tile 32x128 (32 f4/row)
    const int ar = tid >> 3, ac = (tid & 7) * 4;     // 32 rows/pass, 4 passes
    const int br = tid >> 5, bc = (tid & 31) * 4;    // 8 rows/pass, 4 passes

    auto issue_tile = [&](int k0, int st) {
        float* As = sm + st * WSTG;
        float* Bs = As + WBM * WLDA;
        #pragma unroll
        for (int it = 0; it < 4; it++) {
            int r = ar + it * 32;
            cp_async16(As + r * WLDA + ac, A + (long)(m0 + r) * K + k0 + ac);
        }
        #pragma unroll
        for (int it = 0; it < 4; it++) {
            int r = br + it * 8;
            cp_async16(Bs + r * WLDB + bc, B + (long)(k0 + r) * Nn + n0 + bc);
        }
        cp_commit();
    };

    wmma::fragment<wmma::accumulator, 16, 16, 8, float> acc[4][2];
    #pragma unroll
    for (int i = 0; i < 4; i++)
        #pragma unroll
        for (int j = 0; j < 2; j++) wmma::fill_fragment(acc[i][j], 0.0f);

    const int tiles = K / WBK;
    issue_tile(0, 0);

    for (int t = 0; t < tiles; t++) {
        if (t + 1 < tiles) { issue_tile((t + 1) * WBK, (t + 1) & 1); cp_wait<1>(); }
        else               { cp_wait<0>(); }
        __syncthreads();

        const float* As = sm + (t & 1) * WSTG;
        const float* Bs = As + WBM * WLDA;
        #pragma unroll
        for (int kk = 0; kk < WBK; kk += 8) {
            wmma::fragment<wmma::matrix_a, 16, 16, 8, wmma::precision::tf32,
                           wmma::row_major> af[4];
            wmma::fragment<wmma::matrix_b, 16, 16, 8, wmma::precision::tf32,
                           wmma::row_major> bf[2];
            #pragma unroll
            for (int i = 0; i < 4; i++)
                wmma::load_matrix_sync(af[i], As + (wm * 64 + i * 16) * WLDA + kk, WLDA);
            #pragma unroll
            for (int j = 0; j < 2; j++)
                wmma::load_matrix_sync(bf[j], Bs + kk * WLDB + wn * 32 + j * 16, WLDB);
            #pragma unroll
            for (int i = 0; i < 4; i++)
                #pragma unroll
                for (int j = 0; j < 2; j++)
                    wmma::mma_sync(acc[i][j], af[i], bf[j], acc[i][j]);
        }
        __syncthreads();   // stage (t&1) overwritten at t+1's issue
    }

    // epilogue: stage accumulators through smem, add bias (+residual), store
    float* St = sm;                       // 128 x 132 = 16896 floats, fits
    constexpr int ldS = WBN + 4;
    #pragma unroll
    for (int i = 0; i < 4; i++)
        #pragma unroll
        for (int j = 0; j < 2; j++)
            wmma::store_matrix_sync(St + (wm * 64 + i * 16) * ldS + wn * 32 + j * 16,
                                    acc[i][j], ldS, wmma::mem_row_major);
    __syncthreads();
    #pragma unroll
    for (int i = tid; i < WBM * (WBN / 4); i += 256) {
        int r = i >> 5, c = (i & 31) * 4;
        int gm = m0 + r, gn = n0 + c;
        float4 v = *reinterpret_cast<const float4*>(St + r * ldS + c);
        float bv = bias[gm];
        v.x += bv; v.y += bv; v.z += bv; v.w += bv;
        if (EPI == 2) {
            float4 rv = *reinterpret_cast<const float4*>(R + (long)gm * Nn + gn);
            v.x += rv.x; v.y += rv.y; v.z += rv.z; v.w += rv.w;
        }
        *reinterpret_cast<float4*>(C + (long)gm * Nn + gn) = v;
    }
}

// ---------------------------------------------------------------------------
// Fused flash attention (unchanged from R5).
// ---------------------------------------------------------------------------
#define QT 128
#define KT 64
#define QL (QT + 4)
#define KL (KT + 4)
#define SL (KT + 4)

#define OFF_Q  0
#define OFF_K  (OFF_Q + HD * QL)
#define OFF_V  (OFF_K + HD * KL)
#define OFF_S  (OFF_V + HD * KL)
#define OFF_M  (OFF_S + QT * SL)
#define OFF_L  (OFF_M + QT)
#define OFF_A  (OFF_L + QT)
#define FLASH_SMEM_FLOATS (OFF_A + QT)
#define FLASH_SMEM_BYTES  (FLASH_SMEM_FLOATS * 4)

__device__ __forceinline__ unsigned f2u(float f) { return __float_as_uint(f); }

__device__ __forceinline__ void mma_tf32(float& c0, float& c1, float& c2, float& c3,
                                         unsigned a0, unsigned a1, unsigned a2, unsigned a3,
                                         unsigned b0, unsigned b1)
{
    asm volatile(
        "mma.sync.aligned.m16n8k8.row.col.f32.tf32.tf32.f32 "
        "{%0,%1,%2,%3}, {%4,%5,%6,%7}, {%8,%9}, {%0,%1,%2,%3};\n"
        : "+f"(c0), "+f"(c1), "+f"(c2), "+f"(c3)
        : "r"(a0), "r"(a1), "r"(a2), "r"(a3), "r"(b0), "r"(b1));
}

__global__ void __launch_bounds__(256)
flash_kernel(const float* __restrict__ qkv, float* __restrict__ o)
{
    extern __shared__ float sm[];
    float* Qs = sm + OFF_Q;
    float* Ks = sm + OFF_K;
    float* Vs = sm + OFF_V;
    float* Ss = sm + OFF_S;
    float* Ms = sm + OFF_M;
    float* Ls = sm + OFF_L;
    float* Al = sm + OFF_A;

    const int tid  = threadIdx.x;
    const int w    = tid >> 5;
    const int lane = tid & 31;
    const int g    = lane >> 2;
    const int tig  = lane & 3;
    const int wm   = w >> 1;
    const int wn   = w & 1;

    const int q0 = blockIdx.x * QT;
    const int bh = blockIdx.y;
    const long base = ((long)(bh >> 2) * QKV_C + (long)(bh & 3) * HD) * N_;
    const float* Qg = qkv + base;
    const float* Kg = qkv + base + (long)C_ * N_;
    const float* Vg = qkv + base + 2L * (long)C_ * N_;
    float* Og = o + ((long)(bh >> 2) * C_ + (long)(bh & 3) * HD) * N_ + q0;

    const float scale = 0.08838834764831845f;

    #pragma unroll
    for (int i = tid; i < HD * (QT / 4); i += 256) {
        int r = i >> 5, c = i & 31;
        float4 v = *reinterpret_cast<const float4*>(Qg + (long)r * N_ + q0 + c * 4);
        *reinterpret_cast<float4*>(Qs + r * QL + c * 4) = v;
    }
    if (tid < QT) { Ms[tid] = -1e30f; Ls[tid] = 0.f; }

    const int pr = tid >> 4, pc = (tid & 15) * 4;
    float4 pk[8], pv[8];
    #pragma unroll
    for (int it = 0; it < 8; it++) {
        int r = pr + it * 16;
        pk[it] = *reinterpret_cast<const float4*>(Kg + (long)r * N_ + pc);
        pv[it] = *reinterpret_cast<const float4*>(Vg + (long)r * N_ + pc);
    }

    float oc[2][8][4];
    #pragma unroll
    for (int i = 0; i < 2; i++)
        #pragma unroll
        for (int j = 0; j < 8; j++)
            #pragma unroll
            for (int t = 0; t < 4; t++) oc[i][j][t] = 0.f;

    for (int kt = 0; kt < N_ / KT; kt++) {
        __syncthreads();

        #pragma unroll
        for (int it = 0; it < 8; it++) {
            int r = pr + it * 16;
            *reinterpret_cast<float4*>(Ks + r * KL + pc) = pk[it];
            *reinterpret_cast<float4*>(Vs + r * KL + pc) = pv[it];
        }
        if (kt + 1 < N_ / KT) {
            const int k0n = (kt + 1) * KT;
            #pragma unroll
            for (int it = 0; it < 8; it++) {
                int r = pr + it * 16;
                pk[it] = *reinterpret_cast<const float4*>(Kg + (long)r * N_ + k0n + pc);
                pv[it] = *reinterpret_cast<const float4*>(Vg + (long)r * N_ + k0n + pc);
            }
        }
        __syncthreads();

        // S = Q^T K
        {
            wmma::fragment<wmma::accumulator, 16, 16, 8, float> sacc[2][2];
            #pragma unroll
            for (int i = 0; i < 2; i++)
                #pragma unroll
                for (int j = 0; j < 2; j++) wmma::fill_fragment(sacc[i][j], 0.0f);

            #pragma unroll
            for (int kk = 0; kk < HD; kk += 8) {
                wmma::fragment<wmma::matrix_a, 16, 16, 8, wmma::precision::tf32,
                               wmma::col_major> af[2];
                wmma::fragment<wmma::matrix_b, 16, 16, 8, wmma::precision::tf32,
                               wmma::row_major> bf[2];
                #pragma unroll
                for (int i = 0; i < 2; i++)
                    wmma::load_matrix_sync(af[i], Qs + kk * QL + wm * 32 + i * 16, QL);
                #pragma unroll
                for (int j = 0; j < 2; j++)
                    wmma::load_matrix_sync(bf[j], Ks + kk * KL + wn * 32 + j * 16, KL);
                #pragma unroll
                for (int i = 0; i < 2; i++)
                    #pragma unroll
                    for (int j = 0; j < 2; j++)
                        wmma::mma_sync(sacc[i][j], af[i], bf[j], sacc[i][j]);
            }
            #pragma unroll
            for (int i = 0; i < 2; i++)
                #pragma unroll
                for (int j = 0; j < 2; j++) {
                    #pragma unroll
                    for (int t = 0; t < sacc[i][j].num_elements; t++)
                        sacc[i][j].x[t] *= scale;
                    wmma::store_matrix_sync(Ss + (wm * 32 + i * 16) * SL + wn * 32 + j * 16,
                                            sacc[i][j], SL, wmma::mem_row_major);
                }
        }
        __syncthreads();

        // online softmax (2 threads per row)
        {
            const int r    = tid >> 1;
            const int half = tid & 1;
            float* row = Ss + r * SL + half * 32;
            float4 v[8];
            float mx = -1e30f;
            #pragma unroll
            for (int i = 0; i < 8; i++) {
                v[i] = *reinterpret_cast<const float4*>(row + i * 4);
                mx = fmaxf(mx, fmaxf(fmaxf(v[i].x, v[i].y), fmaxf(v[i].z, v[i].w)));
            }
            mx = fmaxf(mx, __shfl_xor_sync(0xffffffffu, mx, 1));
            const float mo = Ms[r];
            const float mn = fmaxf(mo, mx);
            const float alpha = __expf(mo - mn);
            float s = 0.f;
            #pragma unroll
            for (int i = 0; i < 8; i++) {
                v[i].x = __expf(v[i].x - mn); v[i].y = __expf(v[i].y - mn);
                v[i].z = __expf(v[i].z - mn); v[i].w = __expf(v[i].w - mn);
                s += v[i].x + v[i].y + v[i].z + v[i].w;
                *reinterpret_cast<float4*>(row + i * 4) = v[i];
            }
            s += __shfl_xor_sync(0xffffffffu, s, 1);
            if (half == 0) {
                Ms[r] = mn;
                Ls[r] = Ls[r] * alpha + s;
                Al[r] = alpha;
            }
        }
        __syncthreads();

        // rescale O, then O^T += V @ P^T
        {
            const int qb = wn * 64;
            #pragma unroll
            for (int j = 0; j < 8; j++) {
                const float aE = Al[qb + j * 8 + 2 * tig];
                const float aO = Al[qb + j * 8 + 2 * tig + 1];
                #pragma unroll
                for (int i = 0; i < 2; i++) {
                    oc[i][j][0] *= aE; oc[i][j][1] *= aO;
                    oc[i][j][2] *= aE; oc[i][j][3] *= aO;
                }
            }
            #pragma unroll
            for (int kk = 0; kk < KT; kk += 8) {
                unsigned b0[8], b1[8];
                #pragma unroll
                for (int j = 0; j < 8; j++) {
                    const float* prow = Ss + (qb + j * 8 + g) * SL + kk;
                    b0[j] = f2u(prow[tig]);
                    b1[j] = f2u(prow[tig + 4]);
                }
                #pragma unroll
                for (int i = 0; i < 2; i++) {
                    const int dr = wm * 32 + i * 16;
                    const float* vr0 = Vs + (dr + g) * KL + kk;
                    const float* vr1 = Vs + (dr + g + 8) * KL + kk;
                    unsigned a0 = f2u(vr0[tig]);
                    unsigned a1 = f2u(vr1[tig]);
                    unsigned a2 = f2u(vr0[tig + 4]);
                    unsigned a3 = f2u(vr1[tig + 4]);
                    #pragma unroll
                    for (int j = 0; j < 8; j++)
                        mma_tf32(oc[i][j][0], oc[i][j][1], oc[i][j][2], oc[i][j][3],
                                 a0, a1, a2, a3, b0[j], b1[j]);
                }
            }
        }
    }

    // final: /l, store O^T
    {
        const int qb = wn * 64;
        #pragma unroll
        for (int j = 0; j < 8; j++) {
            const int qc = qb + j * 8 + 2 * tig;
            const float iE = 1.0f / Ls[qc];
            const float iO = 1.0f / Ls[qc + 1];
            #pragma unroll
            for (int i = 0; i < 2; i++) {
                const int dr = wm * 32 + i * 16;
                float2 lo = make_float2(oc[i][j][0] * iE, oc[i][j][1] * iO);
                float2 hi = make_float2(oc[i][j][2] * iE, oc[i][j][3] * iO);
                *reinterpret_cast<float2*>(Og + (long)(dr + g) * N_ + qc) = lo;
                *reinterpret_cast<float2*>(Og + (long)(dr + g + 8) * N_ + qc) = hi;
            }
        }
    }
}

// ---------------------------------------------------------------------------
// Launch
// ---------------------------------------------------------------------------
extern "C" void kernel_launch(void* const* d_in, const int* in_sizes, int n_in,
                              void* d_out, int out_size)
{
    const float* x      = (const float*)d_in[0];
    const float* norm_w = (const float*)d_in[1];
    const float* norm_b = (const float*)d_in[2];
    const float* qkv_w  = (const float*)d_in[3];
    const float* qkv_b  = (const float*)d_in[4];
    const float* proj_w = (const float*)d_in[5];
    const float* proj_b = (const float*)d_in[6];
    float* out          = (float*)d_out;

    float *y, *qkv, *o;
    cudaGetSymbolAddress((void**)&y,   g_y);
    cudaGetSymbolAddress((void**)&qkv, g_qkv);
    cudaGetSymbolAddress((void**)&o,   g_o);

    // Idempotent attribute setup (not stream ops; safe under graph capture)
    cudaFuncSetAttribute(flash_kernel,
                         cudaFuncAttributeMaxDynamicSharedMemorySize,
                         FLASH_SMEM_BYTES);
    cudaFuncSetAttribute(wgemm3<1>,
                         cudaFuncAttributeMaxDynamicSharedMemorySize, WSM_BYTES);
    cudaFuncSetAttribute(wgemm3<2>,
                         cudaFuncAttributeMaxDynamicSharedMemorySize, WSM_BYTES);

    // 1) GroupNorm
    groupnorm_kernel<<<B_ * GROUPS, 256>>>(x, norm_w, norm_b, y);

    // 2) QKV: qkv[b](1536,1024) = qkv_w @ y[b] + qkv_b
    {
        dim3 grid(N_ / WBN, QKV_C / WBM, B_);
        wgemm3<1><<<grid, 256, WSM_BYTES>>>(
            qkv_w, y, qkv, QKV_C, C_, N_,
            (long)C_ * N_, (long)QKV_C * N_, qkv_b, nullptr, 0);
    }

    // 3) Fused attention -> o (B, C, N)
    {
        dim3 grid(N_ / QT, B_ * HEADS);
        flash_kernel<<<grid, 256, FLASH_SMEM_BYTES>>>(qkv, o);
    }

    // 4) out[b] = proj_w @ o[b] + proj_b + x[b]
    {
        dim3 grid(N_ / WBN, C_ / WBM, B_);
        wgemm3<2><<<grid, 256, WSM_BYTES>>>(
            proj_w, o, out, C_, C_, N_,
            (long)C_ * N_, (long)C_ * N_, proj_b, x, (long)C_ * N_);
    }
}

// round 9
// speedup vs baseline: 4.2411x; 1.4946x over previous
#include <cuda_runtime.h>
#include <cuda_bf16.h>
#include <mma.h>
#include <math.h>

using namespace nvcuda;

// ---------------------------------------------------------------------------
// Shapes (fixed): x (16, 512, 32, 32) -> B=16, C=512, N=1024; heads=4, hd=128
// ---------------------------------------------------------------------------
#define B_   16
#define C_   512
#define N_   1024
#define HEADS 4
#define HD   128
#define GROUPS 32
#define GSIZE (C_ / GROUPS)
#define QKV_C (3 * C_)

// Scratch (device globals — allocation-free per harness rules)
__device__ __nv_bfloat16 g_y_bf [(size_t)B_ * C_ * N_];
__device__ float         g_qkv  [(size_t)B_ * QKV_C * N_];
__device__ __nv_bfloat16 g_o_bf [(size_t)B_ * C_ * N_];
__device__ __nv_bfloat16 g_wq_bf[(size_t)QKV_C * C_];
__device__ __nv_bfloat16 g_wp_bf[(size_t)C_ * C_];

// ---------------------------------------------------------------------------
// cp.async helpers
// ---------------------------------------------------------------------------
__device__ __forceinline__ void cp_async16(void* smem_dst, const void* gmem_src)
{
    unsigned s = (unsigned)__cvta_generic_to_shared(smem_dst);
    asm volatile("cp.async.cg.shared.global [%0], [%1], 16;\n" :: "r"(s), "l"(gmem_src));
}
__device__ __forceinline__ void cp_commit() { asm volatile("cp.async.commit_group;\n"); }
template<int N> __device__ __forceinline__ void cp_wait()
{ asm volatile("cp.async.wait_group %0;\n" :: "n"(N)); }

// ---------------------------------------------------------------------------
// fp32 -> bf16 conversion (weights), float4-vectorized
// ---------------------------------------------------------------------------
__global__ void cvt_bf16_kernel(const float* __restrict__ a,
                                __nv_bfloat16* __restrict__ o, int n4)
{
    int i = blockIdx.x * blockDim.x + threadIdx.x;
    if (i < n4) {
        float4 v = *reinterpret_cast<const float4*>(a + (size_t)i * 4);
        *reinterpret_cast<__nv_bfloat162*>(o + (size_t)i * 4)     = __floats2bfloat162_rn(v.x, v.y);
        *reinterpret_cast<__nv_bfloat162*>(o + (size_t)i * 4 + 2) = __floats2bfloat162_rn(v.z, v.w);
    }
}

// ---------------------------------------------------------------------------
// GroupNorm -> bf16 output
// ---------------------------------------------------------------------------
__global__ void groupnorm_kernel(const float* __restrict__ x,
                                 const float* __restrict__ w,
                                 const float* __restrict__ bias,
                                 __nv_bfloat16* __restrict__ y)
{
    const int blk = blockIdx.x;
    const int g   = blk % GROUPS;
    const long base = (long)blk * (GSIZE * N_);
    const float* xp = x + base;
    __nv_bfloat16* yp = y + base;

    const int tid = threadIdx.x;
    float s = 0.f, s2 = 0.f;
    #pragma unroll 8
    for (int i = tid; i < GSIZE * N_; i += 256) {
        float v = xp[i];
        s += v; s2 += v * v;
    }
    __shared__ float rs[32], rs2[32];
    for (int off = 16; off > 0; off >>= 1) {
        s  += __shfl_down_sync(0xffffffffu, s,  off);
        s2 += __shfl_down_sync(0xffffffffu, s2, off);
    }
    if ((tid & 31) == 0) { rs[tid >> 5] = s; rs2[tid >> 5] = s2; }
    __syncthreads();
    if (tid < 32) {
        s  = (tid < 8) ? rs[tid]  : 0.f;
        s2 = (tid < 8) ? rs2[tid] : 0.f;
        for (int off = 4; off > 0; off >>= 1) {
            s  += __shfl_down_sync(0xffffffffu, s,  off);
            s2 += __shfl_down_sync(0xffffffffu, s2, off);
        }
        if (tid == 0) { rs[0] = s; rs2[0] = s2; }
    }
    __syncthreads();
    const float inv_n = 1.0f / (GSIZE * N_);
    const float mean  = rs[0] * inv_n;
    const float var   = rs2[0] * inv_n - mean * mean;
    const float rstd  = rsqrtf(var + 1e-5f);

    const int c0 = g * GSIZE;
    #pragma unroll 4
    for (int i = tid; i < GSIZE * N_; i += 256) {
        int ch = c0 + (i >> 10);
        yp[i] = __float2bfloat16((xp[i] - mean) * rstd * w[ch] + bias[ch]);
    }
}

// ---------------------------------------------------------------------------
// 2-stage cp.async BF16 wmma GEMM (m16n16k16, fp32 accumulate):
//   C[z](fp32) = A(MxK bf16) @ B[z](KxN bf16) + bias[m] (+ R[z] fp32)
// BM=128, BN=128, BK=32. 8 warps 2m x 4n; warp tile 64x32 (4x2 frags).
// ---------------------------------------------------------------------------
#define TBM 128
#define TBN 128
#define TBK 32
#define TLDA 40                                   // bf16 elems per A row
#define TLDB 136                                  // bf16 elems per B row
#define TSTG_BYTES (TBM * TLDA * 2 + TBK * TLDB * 2)  // 10240 + 8704 = 18944
#define TSM_BYTES  (TBM * (TBN + 4) * 4)              // 67584 > 2*18944

template<int EPI>   // 1: +bias   2: +bias +residual
__global__ void __launch_bounds__(256, 2)
hgemm(const __nv_bfloat16* __restrict__ A, const __nv_bfloat16* __restrict__ B,
      float* __restrict__ C, int M, int K, int Nn,
      long sB, long sC, const float* __restrict__ bias,
      const float* __restrict__ R, long sR)
{
    extern __shared__ char smraw[];
    const int z = blockIdx.z;
    B += (long)z * sB;
    C += (long)z * sC;
    if (EPI == 2) R += (long)z * sR;

    const int tid = threadIdx.x;
    const int w   = tid >> 5;
    const int wm  = w >> 2;              // 0..1
    const int wn  = w & 3;               // 0..3
    const int m0  = blockIdx.y * TBM;
    const int n0  = blockIdx.x * TBN;

    auto issue_tile = [&](int k0, int st) {
        __nv_bfloat16* As = (__nv_bfloat16*)(smraw + st * TSTG_BYTES);
        __nv_bfloat16* Bs = As + TBM * TLDA;
        // A tile 128x32 bf16 = 512 16B-chunks (4/row)
        #pragma unroll
        for (int it = 0; it < 2; it++) {
            int id = tid + it * 256;
            int r = id >> 2, c = (id & 3) * 8;
            cp_async16(As + r * TLDA + c, A + (long)(m0 + r) * K + k0 + c);
        }
        // B tile 32x128 bf16 = 512 16B-chunks (16/row)
        #pragma unroll
        for (int it = 0; it < 2; it++) {
            int id = tid + it * 256;
            int r = id >> 4, c = (id & 15) * 8;
            cp_async16(Bs + r * TLDB + c, B + (long)(k0 + r) * Nn + n0 + c);
        }
        cp_commit();
    };

    wmma::fragment<wmma::accumulator, 16, 16, 16, float> acc[4][2];
    #pragma unroll
    for (int i = 0; i < 4; i++)
        #pragma unroll
        for (int j = 0; j < 2; j++) wmma::fill_fragment(acc[i][j], 0.0f);

    const int tiles = K / TBK;
    issue_tile(0, 0);

    for (int t = 0; t < tiles; t++) {
        if (t + 1 < tiles) { issue_tile((t + 1) * TBK, (t + 1) & 1); cp_wait<1>(); }
        else               { cp_wait<0>(); }
        __syncthreads();

        const __nv_bfloat16* As = (const __nv_bfloat16*)(smraw + (t & 1) * TSTG_BYTES);
        const __nv_bfloat16* Bs = As + TBM * TLDA;
        #pragma unroll
        for (int ks = 0; ks < 2; ks++) {
            const int kk = ks * 16;
            wmma::fragment<wmma::matrix_a, 16, 16, 16, __nv_bfloat16,
                           wmma::row_major> af[4];
            wmma::fragment<wmma::matrix_b, 16, 16, 16, __nv_bfloat16,
                           wmma::row_major> bfr[2];
            #pragma unroll
            for (int i = 0; i < 4; i++)
                wmma::load_matrix_sync(af[i], As + (wm * 64 + i * 16) * TLDA + kk, TLDA);
            #pragma unroll
            for (int j = 0; j < 2; j++)
                wmma::load_matrix_sync(bfr[j], Bs + kk * TLDB + wn * 32 + j * 16, TLDB);
            #pragma unroll
            for (int i = 0; i < 4; i++)
                #pragma unroll
                for (int j = 0; j < 2; j++)
                    wmma::mma_sync(acc[i][j], af[i], bfr[j], acc[i][j]);
        }
        __syncthreads();
    }

    // epilogue: stage fp32 accumulators through smem, add bias (+residual)
    float* St = (float*)smraw;
    constexpr int ldS = TBN + 4;
    #pragma unroll
    for (int i = 0; i < 4; i++)
        #pragma unroll
        for (int j = 0; j < 2; j++)
            wmma::store_matrix_sync(St + (wm * 64 + i * 16) * ldS + wn * 32 + j * 16,
                                    acc[i][j], ldS, wmma::mem_row_major);
    __syncthreads();
    #pragma unroll
    for (int i = tid; i < TBM * (TBN / 4); i += 256) {
        int r = i >> 5, c = (i & 31) * 4;
        int gm = m0 + r, gn = n0 + c;
        float4 v = *reinterpret_cast<const float4*>(St + r * ldS + c);
        float bv = bias[gm];
        v.x += bv; v.y += bv; v.z += bv; v.w += bv;
        if (EPI == 2) {
            float4 rv = *reinterpret_cast<const float4*>(R + (long)gm * Nn + gn);
            v.x += rv.x; v.y += rv.y; v.z += rv.z; v.w += rv.w;
        }
        *reinterpret_cast<float4*>(C + (long)gm * Nn + gn) = v;
    }
}

// ---------------------------------------------------------------------------
// bf16-output proj-B GEMM needs o in bf16: flash writes bf16 directly.
// Fused flash attention (tf32 math unchanged from R7; only O store -> bf16).
// ---------------------------------------------------------------------------
#define QT 128
#define KT 64
#define QL (QT + 4)
#define KL (KT + 4)
#define SL (KT + 4)

#define OFF_Q  0
#define OFF_K  (OFF_Q + HD * QL)
#define OFF_V  (OFF_K + HD * KL)
#define OFF_S  (OFF_V + HD * KL)
#define OFF_M  (OFF_S + QT * SL)
#define OFF_L  (OFF_M + QT)
#define OFF_A  (OFF_L + QT)
#define FLASH_SMEM_FLOATS (OFF_A + QT)
#define FLASH_SMEM_BYTES  (FLASH_SMEM_FLOATS * 4)

__device__ __forceinline__ unsigned f2u(float f) { return __float_as_uint(f); }

__device__ __forceinline__ void mma_tf32(float& c0, float& c1, float& c2, float& c3,
                                         unsigned a0, unsigned a1, unsigned a2, unsigned a3,
                                         unsigned b0, unsigned b1)
{
    asm volatile(
        "mma.sync.aligned.m16n8k8.row.col.f32.tf32.tf32.f32 "
        "{%0,%1,%2,%3}, {%4,%5,%6,%7}, {%8,%9}, {%0,%1,%2,%3};\n"
        : "+f"(c0), "+f"(c1), "+f"(c2), "+f"(c3)
        : "r"(a0), "r"(a1), "r"(a2), "r"(a3), "r"(b0), "r"(b1));
}

__global__ void __launch_bounds__(256)
flash_kernel(const float* __restrict__ qkv, __nv_bfloat16* __restrict__ o)
{
    extern __shared__ float sm[];
    float* Qs = sm + OFF_Q;
    float* Ks = sm + OFF_K;
    float* Vs = sm + OFF_V;
    float* Ss = sm + OFF_S;
    float* Ms = sm + OFF_M;
    float* Ls = sm + OFF_L;
    float* Al = sm + OFF_A;

    const int tid  = threadIdx.x;
    const int w    = tid >> 5;
    const int lane = tid & 31;
    const int g    = lane >> 2;
    const int tig  = lane & 3;
    const int wm   = w >> 1;
    const int wn   = w & 1;

    const int q0 = blockIdx.x * QT;
    const int bh = blockIdx.y;
    const long base = ((long)(bh >> 2) * QKV_C + (long)(bh & 3) * HD) * N_;
    const float* Qg = qkv + base;
    const float* Kg = qkv + base + (long)C_ * N_;
    const float* Vg = qkv + base + 2L * (long)C_ * N_;
    __nv_bfloat16* Og = o + ((long)(bh >> 2) * C_ + (long)(bh & 3) * HD) * N_ + q0;

    const float scale = 0.08838834764831845f;

    #pragma unroll
    for (int i = tid; i < HD * (QT / 4); i += 256) {
        int r = i >> 5, c = i & 31;
        float4 v = *reinterpret_cast<const float4*>(Qg + (long)r * N_ + q0 + c * 4);
        *reinterpret_cast<float4*>(Qs + r * QL + c * 4) = v;
    }
    if (tid < QT) { Ms[tid] = -1e30f; Ls[tid] = 0.f; }

    const int pr = tid >> 4, pc = (tid & 15) * 4;
    float4 pk[8], pv[8];
    #pragma unroll
    for (int it = 0; it < 8; it++) {
        int r = pr + it * 16;
        pk[it] = *reinterpret_cast<const float4*>(Kg + (long)r * N_ + pc);
        pv[it] = *reinterpret_cast<const float4*>(Vg + (long)r * N_ + pc);
    }

    float oc[2][8][4];
    #pragma unroll
    for (int i = 0; i < 2; i++)
        #pragma unroll
        for (int j = 0; j < 8; j++)
            #pragma unroll
            for (int t = 0; t < 4; t++) oc[i][j][t] = 0.f;

    for (int kt = 0; kt < N_ / KT; kt++) {
        __syncthreads();

        #pragma unroll
        for (int it = 0; it < 8; it++) {
            int r = pr + it * 16;
            *reinterpret_cast<float4*>(Ks + r * KL + pc) = pk[it];
            *reinterpret_cast<float4*>(Vs + r * KL + pc) = pv[it];
        }
        if (kt + 1 < N_ / KT) {
            const int k0n = (kt + 1) * KT;
            #pragma unroll
            for (int it = 0; it < 8; it++) {
                int r = pr + it * 16;
                pk[it] = *reinterpret_cast<const float4*>(Kg + (long)r * N_ + k0n + pc);
                pv[it] = *reinterpret_cast<const float4*>(Vg + (long)r * N_ + k0n + pc);
            }
        }
        __syncthreads();

        // S = Q^T K
        {
            wmma::fragment<wmma::accumulator, 16, 16, 8, float> sacc[2][2];
            #pragma unroll
            for (int i = 0; i < 2; i++)
                #pragma unroll
                for (int j = 0; j < 2; j++) wmma::fill_fragment(sacc[i][j], 0.0f);

            #pragma unroll
            for (int kk = 0; kk < HD; kk += 8) {
                wmma::fragment<wmma::matrix_a, 16, 16, 8, wmma::precision::tf32,
                               wmma::col_major> af[2];
                wmma::fragment<wmma::matrix_b, 16, 16, 8, wmma::precision::tf32,
                               wmma::row_major> bf[2];
                #pragma unroll
                for (int i = 0; i < 2; i++)
                    wmma::load_matrix_sync(af[i], Qs + kk * QL + wm * 32 + i * 16, QL);
                #pragma unroll
                for (int j = 0; j < 2; j++)
                    wmma::load_matrix_sync(bf[j], Ks + kk * KL + wn * 32 + j * 16, KL);
                #pragma unroll
                for (int i = 0; i < 2; i++)
                    #pragma unroll
                    for (int j = 0; j < 2; j++)
                        wmma::mma_sync(sacc[i][j], af[i], bf[j], sacc[i][j]);
            }
            #pragma unroll
            for (int i = 0; i < 2; i++)
                #pragma unroll
                for (int j = 0; j < 2; j++) {
                    #pragma unroll
                    for (int t = 0; t < sacc[i][j].num_elements; t++)
                        sacc[i][j].x[t] *= scale;
                    wmma::store_matrix_sync(Ss + (wm * 32 + i * 16) * SL + wn * 32 + j * 16,
                                            sacc[i][j], SL, wmma::mem_row_major);
                }
        }
        __syncthreads();

        // online softmax (2 threads per row)
        {
            const int r    = tid >> 1;
            const int half = tid & 1;
            float* row = Ss + r * SL + half * 32;
            float4 v[8];
            float mx = -1e30f;
            #pragma unroll
            for (int i = 0; i < 8; i++) {
                v[i] = *reinterpret_cast<const float4*>(row + i * 4);
                mx = fmaxf(mx, fmaxf(fmaxf(v[i].x, v[i].y), fmaxf(v[i].z, v[i].w)));
            }
            mx = fmaxf(mx, __shfl_xor_sync(0xffffffffu, mx, 1));
            const float mo = Ms[r];
            const float mn = fmaxf(mo, mx);
            const float alpha = __expf(mo - mn);
            float s = 0.f;
            #pragma unroll
            for (int i = 0; i < 8; i++) {
                v[i].x = __expf(v[i].x - mn); v[i].y = __expf(v[i].y - mn);
                v[i].z = __expf(v[i].z - mn); v[i].w = __expf(v[i].w - mn);
                s += v[i].x + v[i].y + v[i].z + v[i].w;
                *reinterpret_cast<float4*>(row + i * 4) = v[i];
            }
            s += __shfl_xor_sync(0xffffffffu, s, 1);
            if (half == 0) {
                Ms[r] = mn;
                Ls[r] = Ls[r] * alpha + s;
                Al[r] = alpha;
            }
        }
        __syncthreads();

        // rescale O, then O^T += V @ P^T
        {
            const int qb = wn * 64;
            #pragma unroll
            for (int j = 0; j < 8; j++) {
                const float aE = Al[qb + j * 8 + 2 * tig];
                const float aO = Al[qb + j * 8 + 2 * tig + 1];
                #pragma unroll
                for (int i = 0; i < 2; i++) {
                    oc[i][j][0] *= aE; oc[i][j][1] *= aO;
                    oc[i][j][2] *= aE; oc[i][j][3] *= aO;
                }
            }
            #pragma unroll
            for (int kk = 0; kk < KT; kk += 8) {
                unsigned b0[8], b1[8];
                #pragma unroll
                for (int j = 0; j < 8; j++) {
                    const float* prow = Ss + (qb + j * 8 + g) * SL + kk;
                    b0[j] = f2u(prow[tig]);
                    b1[j] = f2u(prow[tig + 4]);
                }
                #pragma unroll
                for (int i = 0; i < 2; i++) {
                    const int dr = wm * 32 + i * 16;
                    const float* vr0 = Vs + (dr + g) * KL + kk;
                    const float* vr1 = Vs + (dr + g + 8) * KL + kk;
                    unsigned a0 = f2u(vr0[tig]);
                    unsigned a1 = f2u(vr1[tig]);
                    unsigned a2 = f2u(vr0[tig + 4]);
                    unsigned a3 = f2u(vr1[tig + 4]);
                    #pragma unroll
                    for (int j = 0; j < 8; j++)
                        mma_tf32(oc[i][j][0], oc[i][j][1], oc[i][j][2], oc[i][j][3],
                                 a0, a1, a2, a3, b0[j], b1[j]);
                }
            }
        }
    }

    // final: /l, store O^T as bf16 pairs
    {
        const int qb = wn * 64;
        #pragma unroll
        for (int j = 0; j < 8; j++) {
            const int qc = qb + j * 8 + 2 * tig;
            const float iE = 1.0f / Ls[qc];
            const float iO = 1.0f / Ls[qc + 1];
            #pragma unroll
            for (int i = 0; i < 2; i++) {
                const int dr = wm * 32 + i * 16;
                __nv_bfloat162 lo = __floats2bfloat162_rn(oc[i][j][0] * iE, oc[i][j][1] * iO);
                __nv_bfloat162 hi = __floats2bfloat162_rn(oc[i][j][2] * iE, oc[i][j][3] * iO);
                *reinterpret_cast<__nv_bfloat162*>(Og + (long)(dr + g) * N_ + qc) = lo;
                *reinterpret_cast<__nv_bfloat162*>(Og + (long)(dr + g + 8) * N_ + qc) = hi;
            }
        }
    }
}

// ---------------------------------------------------------------------------
// Launch
// ---------------------------------------------------------------------------
extern "C" void kernel_launch(void* const* d_in, const int* in_sizes, int n_in,
                              void* d_out, int out_size)
{
    const float* x      = (const float*)d_in[0];
    const float* norm_w = (const float*)d_in[1];
    const float* norm_b = (const float*)d_in[2];
    const float* qkv_w  = (const float*)d_in[3];
    const float* qkv_b  = (const float*)d_in[4];
    const float* proj_w = (const float*)d_in[5];
    const float* proj_b = (const float*)d_in[6];
    float* out          = (float*)d_out;

    __nv_bfloat16 *y, *o, *wq, *wp;
    float *qkv;
    cudaGetSymbolAddress((void**)&y,   g_y_bf);
    cudaGetSymbolAddress((void**)&qkv, g_qkv);
    cudaGetSymbolAddress((void**)&o,   g_o_bf);
    cudaGetSymbolAddress((void**)&wq,  g_wq_bf);
    cudaGetSymbolAddress((void**)&wp,  g_wp_bf);

    // Idempotent attribute setup (not stream ops; safe under graph capture)
    cudaFuncSetAttribute(flash_kernel,
                         cudaFuncAttributeMaxDynamicSharedMemorySize,
                         FLASH_SMEM_BYTES);
    cudaFuncSetAttribute(hgemm<1>,
                         cudaFuncAttributeMaxDynamicSharedMemorySize, TSM_BYTES);
    cudaFuncSetAttribute(hgemm<2>,
                         cudaFuncAttributeMaxDynamicSharedMemorySize, TSM_BYTES);

    // 0) convert weights to bf16
    cvt_bf16_kernel<<<(QKV_C * C_ / 4 + 255) / 256, 256>>>(qkv_w, wq, QKV_C * C_ / 4);
    cvt_bf16_kernel<<<(C_ * C_ / 4 + 255) / 256, 256>>>(proj_w, wp, C_ * C_ / 4);

    // 1) GroupNorm -> bf16 y
    groupnorm_kernel<<<B_ * GROUPS, 256>>>(x, norm_w, norm_b, y);

    // 2) QKV (bf16 x bf16 -> fp32): qkv[b] = wq @ y[b] + qkv_b
    {
        dim3 grid(N_ / TBN, QKV_C / TBM, B_);
        hgemm<1><<<grid, 256, TSM_BYTES>>>(
            wq, y, qkv, QKV_C, C_, N_,
            (long)C_ * N_, (long)QKV_C * N_, qkv_b, nullptr, 0);
    }

    // 3) Fused attention -> o (bf16, (B, C, N))
    {
        dim3 grid(N_ / QT, B_ * HEADS);
        flash_kernel<<<grid, 256, FLASH_SMEM_BYTES>>>(qkv, o);
    }

    // 4) out[b] = wp @ o[b] + proj_b + x[b]
    {
        dim3 grid(N_ / TBN, C_ / TBM, B_);
        hgemm<2><<<grid, 256, TSM_BYTES>>>(
            wp, o, out, C_, C_, N_,
            (long)C_ * N_, (long)C_ * N_, proj_b, x, (long)C_ * N_);
    }
}

// round 11
// speedup vs baseline: 7.0025x; 1.6511x over previous
#include <cuda_runtime.h>
#include <cuda_bf16.h>
#include <mma.h>
#include <math.h>
#include <string.h>

using namespace nvcuda;

// ---------------------------------------------------------------------------
// Shapes (fixed): x (16, 512, 32, 32) -> B=16, C=512, N=1024; heads=4, hd=128
// ---------------------------------------------------------------------------
#define B_   16
#define C_   512
#define N_   1024
#define HEADS 4
#define HD   128
#define GROUPS 32
#define GSIZE (C_ / GROUPS)
#define QKV_C (3 * C_)

// Scratch (device globals — allocation-free per harness rules)
__device__ __nv_bfloat16 g_y_bf [(size_t)B_ * C_ * N_];
__device__ __nv_bfloat16 g_qkv  [(size_t)B_ * QKV_C * N_];
__device__ __nv_bfloat16 g_o_bf [(size_t)B_ * C_ * N_];
__device__ __nv_bfloat16 g_wq_bf[(size_t)QKV_C * C_];
__device__ __nv_bfloat16 g_wp_bf[(size_t)C_ * C_];

// ---------------------------------------------------------------------------
// helpers
// ---------------------------------------------------------------------------
__device__ __forceinline__ unsigned bf2_bits(__nv_bfloat162 v)
{
    unsigned u;
    memcpy(&u, &v, 4);
    return u;
}

__device__ __forceinline__ void cp_async16(void* smem_dst, const void* gmem_src)
{
    unsigned s = (unsigned)__cvta_generic_to_shared(smem_dst);
    asm volatile("cp.async.cg.shared.global [%0], [%1], 16;\n" :: "r"(s), "l"(gmem_src));
}
__device__ __forceinline__ void cp_commit() { asm volatile("cp.async.commit_group;\n"); }
template<int N> __device__ __forceinline__ void cp_wait()
{ asm volatile("cp.async.wait_group %0;\n" :: "n"(N)); }

// ---------------------------------------------------------------------------
// fp32 -> bf16 conversion (weights)
// ---------------------------------------------------------------------------
__global__ void cvt_bf16_kernel(const float* __restrict__ a,
                                __nv_bfloat16* __restrict__ o, int n4)
{
    int i = blockIdx.x * blockDim.x + threadIdx.x;
    if (i < n4) {
        float4 v = *reinterpret_cast<const float4*>(a + (size_t)i * 4);
        *reinterpret_cast<__nv_bfloat162*>(o + (size_t)i * 4)     = __floats2bfloat162_rn(v.x, v.y);
        *reinterpret_cast<__nv_bfloat162*>(o + (size_t)i * 4 + 2) = __floats2bfloat162_rn(v.z, v.w);
    }
}

// ---------------------------------------------------------------------------
// GroupNorm -> bf16 output
// ---------------------------------------------------------------------------
__global__ void groupnorm_kernel(const float* __restrict__ x,
                                 const float* __restrict__ w,
                                 const float* __restrict__ bias,
                                 __nv_bfloat16* __restrict__ y)
{
    const int blk = blockIdx.x;
    const int g   = blk % GROUPS;
    const long base = (long)blk * (GSIZE * N_);
    const float* xp = x + base;
    __nv_bfloat16* yp = y + base;

    const int tid = threadIdx.x;
    float s = 0.f, s2 = 0.f;
    #pragma unroll 8
    for (int i = tid; i < GSIZE * N_; i += 256) {
        float v = xp[i];
        s += v; s2 += v * v;
    }
    __shared__ float rs[32], rs2[32];
    for (int off = 16; off > 0; off >>= 1) {
        s  += __shfl_down_sync(0xffffffffu, s,  off);
        s2 += __shfl_down_sync(0xffffffffu, s2, off);
    }
    if ((tid & 31) == 0) { rs[tid >> 5] = s; rs2[tid >> 5] = s2; }
    __syncthreads();
    if (tid < 32) {
        s  = (tid < 8) ? rs[tid]  : 0.f;
        s2 = (tid < 8) ? rs2[tid] : 0.f;
        for (int off = 4; off > 0; off >>= 1) {
            s  += __shfl_down_sync(0xffffffffu, s,  off);
            s2 += __shfl_down_sync(0xffffffffu, s2, off);
        }
        if (tid == 0) { rs[0] = s; rs2[0] = s2; }
    }
    __syncthreads();
    const float inv_n = 1.0f / (GSIZE * N_);
    const float mean  = rs[0] * inv_n;
    const float var   = rs2[0] * inv_n - mean * mean;
    const float rstd  = rsqrtf(var + 1e-5f);

    const int c0 = g * GSIZE;
    #pragma unroll 4
    for (int i = tid; i < GSIZE * N_; i += 256) {
        int ch = c0 + (i >> 10);
        yp[i] = __float2bfloat16((xp[i] - mean) * rstd * w[ch] + bias[ch]);
    }
}

// ---------------------------------------------------------------------------
// 2-stage cp.async BF16 wmma GEMM (m16n16k16, fp32 accumulate):
//   C[z] = A(MxK bf16) @ B[z](KxN bf16) + bias[m] (+ R[z] fp32)
// OUTB: write bf16 (for qkv), else fp32 (final output with residual)
// ---------------------------------------------------------------------------
#define TBM 128
#define TBN 128
#define TBK 32
#define TLDA 40
#define TLDB 136
#define TSTG_BYTES (TBM * TLDA * 2 + TBK * TLDB * 2)  // 18944
#define TSM_BYTES  (TBM * (TBN + 4) * 4)              // 67584 > 2*18944

template<int EPI, bool OUTB>   // EPI 1: +bias   2: +bias +residual
__global__ void __launch_bounds__(256, 2)
hgemm(const __nv_bfloat16* __restrict__ A, const __nv_bfloat16* __restrict__ B,
      void* __restrict__ Cv, int M, int K, int Nn,
      long sB, long sC, const float* __restrict__ bias,
      const float* __restrict__ R, long sR)
{
    extern __shared__ char smraw[];
    const int z = blockIdx.z;
    B += (long)z * sB;
    if (EPI == 2) R += (long)z * sR;

    const int tid = threadIdx.x;
    const int w   = tid >> 5;
    const int wm  = w >> 2;
    const int wn  = w & 3;
    const int m0  = blockIdx.y * TBM;
    const int n0  = blockIdx.x * TBN;

    auto issue_tile = [&](int k0, int st) {
        __nv_bfloat16* As = (__nv_bfloat16*)(smraw + st * TSTG_BYTES);
        __nv_bfloat16* Bs = As + TBM * TLDA;
        #pragma unroll
        for (int it = 0; it < 2; it++) {
            int id = tid + it * 256;
            int r = id >> 2, c = (id & 3) * 8;
            cp_async16(As + r * TLDA + c, A + (long)(m0 + r) * K + k0 + c);
        }
        #pragma unroll
        for (int it = 0; it < 2; it++) {
            int id = tid + it * 256;
            int r = id >> 4, c = (id & 15) * 8;
            cp_async16(Bs + r * TLDB + c, B + (long)(k0 + r) * Nn + n0 + c);
        }
        cp_commit();
    };

    wmma::fragment<wmma::accumulator, 16, 16, 16, float> acc[4][2];
    #pragma unroll
    for (int i = 0; i < 4; i++)
        #pragma unroll
        for (int j = 0; j < 2; j++) wmma::fill_fragment(acc[i][j], 0.0f);

    const int tiles = K / TBK;
    issue_tile(0, 0);

    for (int t = 0; t < tiles; t++) {
        if (t + 1 < tiles) { issue_tile((t + 1) * TBK, (t + 1) & 1); cp_wait<1>(); }
        else               { cp_wait<0>(); }
        __syncthreads();

        const __nv_bfloat16* As = (const __nv_bfloat16*)(smraw + (t & 1) * TSTG_BYTES);
        const __nv_bfloat16* Bs = As + TBM * TLDA;
        #pragma unroll
        for (int ks = 0; ks < 2; ks++) {
            const int kk = ks * 16;
            wmma::fragment<wmma::matrix_a, 16, 16, 16, __nv_bfloat16,
                           wmma::row_major> af[4];
            wmma::fragment<wmma::matrix_b, 16, 16, 16, __nv_bfloat16,
                           wmma::row_major> bfr[2];
            #pragma unroll
            for (int i = 0; i < 4; i++)
                wmma::load_matrix_sync(af[i], As + (wm * 64 + i * 16) * TLDA + kk, TLDA);
            #pragma unroll
            for (int j = 0; j < 2; j++)
                wmma::load_matrix_sync(bfr[j], Bs + kk * TLDB + wn * 32 + j * 16, TLDB);
            #pragma unroll
            for (int i = 0; i < 4; i++)
                #pragma unroll
                for (int j = 0; j < 2; j++)
                    wmma::mma_sync(acc[i][j], af[i], bfr[j], acc[i][j]);
        }
        __syncthreads();
    }

    float* St = (float*)smraw;
    constexpr int ldS = TBN + 4;
    #pragma unroll
    for (int i = 0; i < 4; i++)
        #pragma unroll
        for (int j = 0; j < 2; j++)
            wmma::store_matrix_sync(St + (wm * 64 + i * 16) * ldS + wn * 32 + j * 16,
                                    acc[i][j], ldS, wmma::mem_row_major);
    __syncthreads();
    #pragma unroll
    for (int i = tid; i < TBM * (TBN / 4); i += 256) {
        int r = i >> 5, c = (i & 31) * 4;
        int gm = m0 + r, gn = n0 + c;
        float4 v = *reinterpret_cast<const float4*>(St + r * ldS + c);
        float bv = bias[gm];
        v.x += bv; v.y += bv; v.z += bv; v.w += bv;
        if (EPI == 2) {
            float4 rv = *reinterpret_cast<const float4*>(R + (long)gm * Nn + gn);
            v.x += rv.x; v.y += rv.y; v.z += rv.z; v.w += rv.w;
        }
        if (OUTB) {
            __nv_bfloat16* C = (__nv_bfloat16*)Cv + (long)z * sC;
            uint2 p;
            p.x = bf2_bits(__floats2bfloat162_rn(v.x, v.y));
            p.y = bf2_bits(__floats2bfloat162_rn(v.z, v.w));
            *reinterpret_cast<uint2*>(C + (long)gm * Nn + gn) = p;
        } else {
            float* C = (float*)Cv + (long)z * sC;
            *reinterpret_cast<float4*>(C + (long)gm * Nn + gn) = v;
        }
    }
}

// ---------------------------------------------------------------------------
// Fused flash attention, all-bf16 operands (fp32 accumulate & softmax).
//   Q/K/V tiles bf16 in smem; S computed by wmma bf16 m16n16k16 into fp32 Ss;
//   softmax writes P bf16 to Sp; PV uses raw mma.m16n8k16 bf16.
// ---------------------------------------------------------------------------
#define QT 128
#define KT 64
#define QLH 136                 // Q smem row (bf16 elems)
#define KLH 72                  // K/V smem row
#define SL  68                  // Ss fp32 row
#define SPL 72                  // Sp bf16 row

#define OFB_Q  0
#define OFB_K  (OFB_Q + HD * QLH * 2)       // 34816
#define OFB_V  (OFB_K + HD * KLH * 2)       // 53248
#define OFB_SS (OFB_V + HD * KLH * 2)       // 71680
#define OFB_SP (OFB_SS + QT * SL * 4)       // 106496
#define OFB_M  (OFB_SP + QT * SPL * 2)      // 124928
#define OFB_L  (OFB_M + QT * 4)
#define OFB_A  (OFB_L + QT * 4)
#define FLASH_SMEM_BYTES (OFB_A + QT * 4)   // 126464

__device__ __forceinline__ void mma_bf16(float& c0, float& c1, float& c2, float& c3,
                                         unsigned a0, unsigned a1, unsigned a2, unsigned a3,
                                         unsigned b0, unsigned b1)
{
    asm volatile(
        "mma.sync.aligned.m16n8k16.row.col.f32.bf16.bf16.f32 "
        "{%0,%1,%2,%3}, {%4,%5,%6,%7}, {%8,%9}, {%0,%1,%2,%3};\n"
        : "+f"(c0), "+f"(c1), "+f"(c2), "+f"(c3)
        : "r"(a0), "r"(a1), "r"(a2), "r"(a3), "r"(b0), "r"(b1));
}

__global__ void __launch_bounds__(256)
flash_kernel(const __nv_bfloat16* __restrict__ qkv, __nv_bfloat16* __restrict__ o)
{
    extern __shared__ char smc[];
    __nv_bfloat16* Qs = (__nv_bfloat16*)(smc + OFB_Q);
    __nv_bfloat16* Ks = (__nv_bfloat16*)(smc + OFB_K);
    __nv_bfloat16* Vs = (__nv_bfloat16*)(smc + OFB_V);
    float*         Ss = (float*)(smc + OFB_SS);
    __nv_bfloat16* Sp = (__nv_bfloat16*)(smc + OFB_SP);
    float*         Ms = (float*)(smc + OFB_M);
    float*         Ls = (float*)(smc + OFB_L);
    float*         Al = (float*)(smc + OFB_A);

    const int tid  = threadIdx.x;
    const int w    = tid >> 5;
    const int lane = tid & 31;
    const int g    = lane >> 2;
    const int tig  = lane & 3;
    const int wm   = w >> 1;
    const int wn   = w & 1;

    const int q0 = blockIdx.x * QT;
    const int bh = blockIdx.y;
    const long base = ((long)(bh >> 2) * QKV_C + (long)(bh & 3) * HD) * N_;
    const __nv_bfloat16* Qg = qkv + base;
    const __nv_bfloat16* Kg = qkv + base + (long)C_ * N_;
    const __nv_bfloat16* Vg = qkv + base + 2L * (long)C_ * N_;
    __nv_bfloat16* Og = o + ((long)(bh >> 2) * C_ + (long)(bh & 3) * HD) * N_ + q0;

    const float scale = 0.08838834764831845f;

    // Q tile [128 d][128 q] bf16 (16B chunks, 8/thread)
    #pragma unroll
    for (int i = tid; i < HD * 16; i += 256) {
        int r = i >> 4, c = (i & 15) * 8;
        *reinterpret_cast<uint4*>(Qs + r * QLH + c) =
            *reinterpret_cast<const uint4*>(Qg + (long)r * N_ + q0 + c);
    }
    if (tid < QT) { Ms[tid] = -1e30f; Ls[tid] = 0.f; }

    // K/V prefetch: per thread 4 chunks of 8 bf16 each tile
    const int pr = tid >> 3, pc = (tid & 7) * 8;
    uint4 pk[4], pv[4];
    #pragma unroll
    for (int it = 0; it < 4; it++) {
        int r = pr + it * 32;
        pk[it] = *reinterpret_cast<const uint4*>(Kg + (long)r * N_ + pc);
        pv[it] = *reinterpret_cast<const uint4*>(Vg + (long)r * N_ + pc);
    }

    float oc[2][8][4];
    #pragma unroll
    for (int i = 0; i < 2; i++)
        #pragma unroll
        for (int j = 0; j < 8; j++)
            #pragma unroll
            for (int t = 0; t < 4; t++) oc[i][j][t] = 0.f;

    for (int kt = 0; kt < N_ / KT; kt++) {
        __syncthreads();

        #pragma unroll
        for (int it = 0; it < 4; it++) {
            int r = pr + it * 32;
            *reinterpret_cast<uint4*>(Ks + r * KLH + pc) = pk[it];
            *reinterpret_cast<uint4*>(Vs + r * KLH + pc) = pv[it];
        }
        if (kt + 1 < N_ / KT) {
            const int k0n = (kt + 1) * KT;
            #pragma unroll
            for (int it = 0; it < 4; it++) {
                int r = pr + it * 32;
                pk[it] = *reinterpret_cast<const uint4*>(Kg + (long)r * N_ + k0n + pc);
                pv[it] = *reinterpret_cast<const uint4*>(Vg + (long)r * N_ + k0n + pc);
            }
        }
        __syncthreads();

        // S = Q^T K  (bf16 wmma m16n16k16, fp32 accum)
        {
            wmma::fragment<wmma::accumulator, 16, 16, 16, float> sacc[2][2];
            #pragma unroll
            for (int i = 0; i < 2; i++)
                #pragma unroll
                for (int j = 0; j < 2; j++) wmma::fill_fragment(sacc[i][j], 0.0f);

            #pragma unroll
            for (int kk = 0; kk < HD; kk += 16) {
                wmma::fragment<wmma::matrix_a, 16, 16, 16, __nv_bfloat16,
                               wmma::col_major> af[2];
                wmma::fragment<wmma::matrix_b, 16, 16, 16, __nv_bfloat16,
                               wmma::row_major> bf[2];
                #pragma unroll
                for (int i = 0; i < 2; i++)
                    wmma::load_matrix_sync(af[i], Qs + kk * QLH + wm * 32 + i * 16, QLH);
                #pragma unroll
                for (int j = 0; j < 2; j++)
                    wmma::load_matrix_sync(bf[j], Ks + kk * KLH + wn * 32 + j * 16, KLH);
                #pragma unroll
                for (int i = 0; i < 2; i++)
                    #pragma unroll
                    for (int j = 0; j < 2; j++)
                        wmma::mma_sync(sacc[i][j], af[i], bf[j], sacc[i][j]);
            }
            #pragma unroll
            for (int i = 0; i < 2; i++)
                #pragma unroll
                for (int j = 0; j < 2; j++) {
                    #pragma unroll
                    for (int t = 0; t < sacc[i][j].num_elements; t++)
                        sacc[i][j].x[t] *= scale;
                    wmma::store_matrix_sync(Ss + (wm * 32 + i * 16) * SL + wn * 32 + j * 16,
                                            sacc[i][j], SL, wmma::mem_row_major);
                }
        }
        __syncthreads();

        // online softmax; write P to Sp as bf16
        {
            const int r    = tid >> 1;
            const int half = tid & 1;
            float* row = Ss + r * SL + half * 32;
            __nv_bfloat16* prow = Sp + r * SPL + half * 32;
            float4 v[8];
            float mx = -1e30f;
            #pragma unroll
            for (int i = 0; i < 8; i++) {
                v[i] = *reinterpret_cast<const float4*>(row + i * 4);
                mx = fmaxf(mx, fmaxf(fmaxf(v[i].x, v[i].y), fmaxf(v[i].z, v[i].w)));
            }
            mx = fmaxf(mx, __shfl_xor_sync(0xffffffffu, mx, 1));
            const float mo = Ms[r];
            const float mn = fmaxf(mo, mx);
            const float alpha = __expf(mo - mn);
            float s = 0.f;
            #pragma unroll
            for (int i = 0; i < 8; i++) {
                v[i].x = __expf(v[i].x - mn); v[i].y = __expf(v[i].y - mn);
                v[i].z = __expf(v[i].z - mn); v[i].w = __expf(v[i].w - mn);
                s += v[i].x + v[i].y + v[i].z + v[i].w;
                uint2 p;
                p.x = bf2_bits(__floats2bfloat162_rn(v[i].x, v[i].y));
                p.y = bf2_bits(__floats2bfloat162_rn(v[i].z, v[i].w));
                *reinterpret_cast<uint2*>(prow + i * 4) = p;
            }
            s += __shfl_xor_sync(0xffffffffu, s, 1);
            if (half == 0) {
                Ms[r] = mn;
                Ls[r] = Ls[r] * alpha + s;
                Al[r] = alpha;
            }
        }
        __syncthreads();

        // rescale O by alpha, then O^T += V @ P^T  (bf16 m16n8k16)
        {
            const int qb = wn * 64;
            #pragma unroll
            for (int j = 0; j < 8; j++) {
                const float aE = Al[qb + j * 8 + 2 * tig];
                const float aO = Al[qb + j * 8 + 2 * tig + 1];
                #pragma unroll
                for (int i = 0; i < 2; i++) {
                    oc[i][j][0] *= aE; oc[i][j][1] *= aO;
                    oc[i][j][2] *= aE; oc[i][j][3] *= aO;
                }
            }
            #pragma unroll
            for (int kk = 0; kk < KT; kk += 16) {
                unsigned b0[8], b1[8];
                #pragma unroll
                for (int j = 0; j < 8; j++) {
                    const __nv_bfloat16* pr2 = Sp + (qb + j * 8 + g) * SPL + kk;
                    b0[j] = *reinterpret_cast<const unsigned*>(pr2 + 2 * tig);
                    b1[j] = *reinterpret_cast<const unsigned*>(pr2 + 8 + 2 * tig);
                }
                #pragma unroll
                for (int i = 0; i < 2; i++) {
                    const int dr = wm * 32 + i * 16;
                    const __nv_bfloat16* vr0 = Vs + (dr + g) * KLH + kk;
                    const __nv_bfloat16* vr1 = Vs + (dr + g + 8) * KLH + kk;
                    unsigned a0 = *reinterpret_cast<const unsigned*>(vr0 + 2 * tig);
                    unsigned a1 = *reinterpret_cast<const unsigned*>(vr1 + 2 * tig);
                    unsigned a2 = *reinterpret_cast<const unsigned*>(vr0 + 8 + 2 * tig);
                    unsigned a3 = *reinterpret_cast<const unsigned*>(vr1 + 8 + 2 * tig);
                    #pragma unroll
                    for (int j = 0; j < 8; j++)
                        mma_bf16(oc[i][j][0], oc[i][j][1], oc[i][j][2], oc[i][j][3],
                                 a0, a1, a2, a3, b0[j], b1[j]);
                }
            }
        }
    }

    // final: /l, store O^T as bf16 pairs
    {
        const int qb = wn * 64;
        #pragma unroll
        for (int j = 0; j < 8; j++) {
            const int qc = qb + j * 8 + 2 * tig;
            const float iE = 1.0f / Ls[qc];
            const float iO = 1.0f / Ls[qc + 1];
            #pragma unroll
            for (int i = 0; i < 2; i++) {
                const int dr = wm * 32 + i * 16;
                __nv_bfloat162 lo = __floats2bfloat162_rn(oc[i][j][0] * iE, oc[i][j][1] * iO);
                __nv_bfloat162 hi = __floats2bfloat162_rn(oc[i][j][2] * iE, oc[i][j][3] * iO);
                *reinterpret_cast<__nv_bfloat162*>(Og + (long)(dr + g) * N_ + qc) = lo;
                *reinterpret_cast<__nv_bfloat162*>(Og + (long)(dr + g + 8) * N_ + qc) = hi;
            }
        }
    }
}

// ---------------------------------------------------------------------------
// Launch
// ---------------------------------------------------------------------------
extern "C" void kernel_launch(void* const* d_in, const int* in_sizes, int n_in,
                              void* d_out, int out_size)
{
    const float* x      = (const float*)d_in[0];
    const float* norm_w = (const float*)d_in[1];
    const float* norm_b = (const float*)d_in[2];
    const float* qkv_w  = (const float*)d_in[3];
    const float* qkv_b  = (const float*)d_in[4];
    const float* proj_w = (const float*)d_in[5];
    const float* proj_b = (const float*)d_in[6];
    float* out          = (float*)d_out;

    __nv_bfloat16 *y, *o, *wq, *wp, *qkv;
    cudaGetSymbolAddress((void**)&y,   g_y_bf);
    cudaGetSymbolAddress((void**)&qkv, g_qkv);
    cudaGetSymbolAddress((void**)&o,   g_o_bf);
    cudaGetSymbolAddress((void**)&wq,  g_wq_bf);
    cudaGetSymbolAddress((void**)&wp,  g_wp_bf);

    // Idempotent attribute setup (not stream ops; safe under graph capture)
    cudaFuncSetAttribute(flash_kernel,
                         cudaFuncAttributeMaxDynamicSharedMemorySize,
                         FLASH_SMEM_BYTES);
    cudaFuncSetAttribute(hgemm<1, true>,
                         cudaFuncAttributeMaxDynamicSharedMemorySize, TSM_BYTES);
    cudaFuncSetAttribute(hgemm<2, false>,
                         cudaFuncAttributeMaxDynamicSharedMemorySize, TSM_BYTES);

    // 0) convert weights to bf16
    cvt_bf16_kernel<<<(QKV_C * C_ / 4 + 255) / 256, 256>>>(qkv_w, wq, QKV_C * C_ / 4);
    cvt_bf16_kernel<<<(C_ * C_ / 4 + 255) / 256, 256>>>(proj_w, wp, C_ * C_ / 4);

    // 1) GroupNorm -> bf16 y
    groupnorm_kernel<<<B_ * GROUPS, 256>>>(x, norm_w, norm_b, y);

    // 2) QKV (bf16 -> bf16): qkv[b] = wq @ y[b] + qkv_b
    {
        dim3 grid(N_ / TBN, QKV_C / TBM, B_);
        hgemm<1, true><<<grid, 256, TSM_BYTES>>>(
            wq, y, qkv, QKV_C, C_, N_,
            (long)C_ * N_, (long)QKV_C * N_, qkv_b, nullptr, 0);
    }

    // 3) Fused attention (all-bf16 operands) -> o
    {
        dim3 grid(N_ / QT, B_ * HEADS);
        flash_kernel<<<grid, 256, FLASH_SMEM_BYTES>>>(qkv, o);
    }

    // 4) out[b] = wp @ o[b] + proj_b + x[b]  (fp32 out)
    {
        dim3 grid(N_ / TBN, C_ / TBM, B_);
        hgemm<2, false><<<grid, 256, TSM_BYTES>>>(
            wp, o, out, C_, C_, N_,
            (long)C_ * N_, (long)C_ * N_, proj_b, x, (long)C_ * N_);
    }
}